// round 13
// baseline (speedup 1.0000x reference)
#include <cuda_runtime.h>
#include <cuda_fp16.h>
#include <cstdint>

#define Bsz 16384
#define Fn 26
#define Nrows 100000
#define Dim 64
#define Lk 4
#define NFEAT 27
#define NPAIRS 351
#define OVERIN 415
#define YSTR 416
#define LDA 40
#define ILD 72

// phase grids: all 425984 gather warp-tasks split between phase_a and phase_b
#define NSPL 1920
#define NB0  1024
#define GA_BLK 26624          // 8 tasks per 256-thr block
#define GB_BLK 26624
#define GA_TASKS (GA_BLK * 8) // 212992

// ---------------- scratch -----------------------------------------------------
__device__ float  g_feats[(size_t)Bsz * NFEAT * Dim];
__device__ __half g_h1[(size_t)Bsz * 512];
__device__ __half g_h2[(size_t)Bsz * 256];
__device__ __half g_y[(size_t)Bsz * YSTR];
__device__ __half g_w1[256 * 512];
__device__ __half g_w2[64 * 256];
__device__ __half g_t0[512 * YSTR];
__device__ __half g_t1[256 * 512];

#define MMA_F16(c, a, b0v, b1v) \
    asm volatile("mma.sync.aligned.m16n8k16.row.col.f32.f16.f16.f32 " \
        "{%0,%1,%2,%3}, {%4,%5,%6,%7}, {%8,%9}, {%0,%1,%2,%3};" \
        : "+f"((c)[0]), "+f"((c)[1]), "+f"((c)[2]), "+f"((c)[3]) \
        : "r"((a)[0]), "r"((a)[1]), "r"((a)[2]), "r"((a)[3]), "r"(b0v), "r"(b1v))

// ---- 32-K mma chunk: As rows x LDA, Bs[64][LDA], scalar frag loads -----------
__device__ __forceinline__ void mma_chunk(const __half* As, const __half* Bs,
    int wm, int wn, int gid, int tig, float acc[2][4][4])
{
    #pragma unroll
    for (int ks = 0; ks < 32; ks += 16) {
        uint32_t a[2][4], bh[4][2];
        #pragma unroll
        for (int mt = 0; mt < 2; mt++) {
            int r0 = (wm * 32 + mt * 16 + gid) * LDA + ks + 2 * tig;
            a[mt][0] = *(const uint32_t*)&As[r0];
            a[mt][1] = *(const uint32_t*)&As[r0 + 8 * LDA];
            a[mt][2] = *(const uint32_t*)&As[r0 + 8];
            a[mt][3] = *(const uint32_t*)&As[r0 + 8 * LDA + 8];
        }
        #pragma unroll
        for (int nt = 0; nt < 4; nt++) {
            int n0 = (wn * 32 + nt * 8 + gid) * LDA + ks + 2 * tig;
            bh[nt][0] = *(const uint32_t*)&Bs[n0];
            bh[nt][1] = *(const uint32_t*)&Bs[n0 + 8];
        }
        #pragma unroll
        for (int mt = 0; mt < 2; mt++)
            #pragma unroll
            for (int nt = 0; nt < 4; nt++)
                MMA_F16(acc[mt][nt], a[mt], bh[nt][0], bh[nt][1]);
    }
}

__device__ __forceinline__ void gemm_epi(float acc[2][4][4],
    const float* __restrict__ bias, int bm, int bn, int wm, int wn,
    int gid, int tig, int relu, int outmode,
    float* __restrict__ Cf, int ldcf, __half* __restrict__ Ch, int ldch)
{
    #pragma unroll
    for (int mt = 0; mt < 2; mt++) {
        int r0 = bm + wm * 32 + mt * 16 + gid;
        #pragma unroll
        for (int nt = 0; nt < 4; nt++) {
            int cc = bn + wn * 32 + nt * 8 + tig * 2;
            float b0 = bias[cc], b1 = bias[cc + 1];
            float v00 = acc[mt][nt][0] + b0, v01 = acc[mt][nt][1] + b1;
            float v10 = acc[mt][nt][2] + b0, v11 = acc[mt][nt][3] + b1;
            if (relu) {
                v00 = fmaxf(v00, 0.f); v01 = fmaxf(v01, 0.f);
                v10 = fmaxf(v10, 0.f); v11 = fmaxf(v11, 0.f);
            }
            if (outmode == 0) {
                *(float2*)&Cf[(size_t)r0 * ldcf + cc]       = make_float2(v00, v01);
                *(float2*)&Cf[(size_t)(r0 + 8) * ldcf + cc] = make_float2(v10, v11);
            } else {
                *(__half2*)&Ch[(size_t)r0 * ldch + cc]       = __floats2half2_rn(v00, v01);
                *(__half2*)&Ch[(size_t)(r0 + 8) * ldch + cc] = __floats2half2_rn(v10, v11);
            }
        }
    }
}

// ---- GEMM core: CTA 128x64, 256 thr, double-buffered, 1 sync / K-iter --------
__device__ void gemm_core(__half* sm0, const __half* __restrict__ A,
    const __half* __restrict__ B, const float* __restrict__ bias, int K,
    int bx, int by, __half* __restrict__ Ch, int ldch)
{
    const int tid = threadIdx.x, warp = tid >> 5, lane = tid & 31;
    const int wm = warp & 3, wn = warp >> 2;
    const int gid = lane >> 2, tig = lane & 3;
    const int bm = by * 128, bn = bx * 64;

    float acc[2][4][4] = {};
    const int kIter = K >> 5;
    uint4 pa[2], pb;

    auto prefetch = [&](int it) {
        const int k0 = it * 32;
        #pragma unroll
        for (int s = 0; s < 2; s++) {
            int idx = tid + s * 256;
            int r = idx >> 2, kq = idx & 3;
            pa[s] = *(const uint4*)(A + (size_t)(bm + r) * K + k0 + kq * 8);
        }
        {
            int n = tid >> 2, kq = tid & 3;
            pb = *(const uint4*)(B + (size_t)(bn + n) * K + k0 + kq * 8);
        }
    };

    prefetch(0);
    for (int it = 0; it < kIter; it++) {
        __half* As = sm0 + (it & 1) * 7680;
        __half* Bs = As + 5120;
        #pragma unroll
        for (int s = 0; s < 2; s++) {
            int idx = tid + s * 256;
            int r = idx >> 2, kq = idx & 3;
            *(uint4*)&As[r * LDA + kq * 8] = pa[s];
        }
        {
            int n = tid >> 2, kq = tid & 3;
            *(uint4*)&Bs[n * LDA + kq * 8] = pb;
        }
        __syncthreads();
        if (it + 1 < kIter) prefetch(it + 1);
        mma_chunk(As, Bs, wm, wn, gid, tig, acc);
    }
    gemm_epi(acc, bias, bm, bn, wm, wn, gid, tig, 1, 1, nullptr, 0, Ch, ldch);
}

// ---- b0 role: K=32 (13 real), fp32 inputs converted inline --------------------
__device__ void b0_role(__half* sm0, int blk, const float* __restrict__ dense,
    const float* __restrict__ W0, const float* __restrict__ bias,
    __half* __restrict__ h1)
{
    __half* As = sm0;
    __half* Bs = sm0 + 5120;
    const int tid = threadIdx.x, warp = tid >> 5, lane = tid & 31;
    const int wm = warp & 3, wn = warp >> 2;
    const int gid = lane >> 2, tig = lane & 3;
    const int by = blk >> 3, bx = blk & 7;
    const int bm = by * 128, bn = bx * 64;

    #pragma unroll
    for (int s = 0; s < 8; s++) {
        int idx = tid + s * 256;
        int r = idx >> 4, cp = (idx & 15) * 2;
        float x0 = (cp < 13)     ? dense[(size_t)(bm + r) * 13 + cp]     : 0.f;
        float x1 = (cp + 1 < 13) ? dense[(size_t)(bm + r) * 13 + cp + 1] : 0.f;
        *(__half2*)&As[r * LDA + cp] = __floats2half2_rn(x0, x1);
    }
    #pragma unroll
    for (int s = 0; s < 8; s++) {
        int idx = tid + s * 256;
        int n = idx & 63, k = idx >> 6;
        float v = (k < 13) ? W0[(size_t)k * 512 + bn + n] : 0.f;
        Bs[n * LDA + k] = __float2half_rn(v);
    }
    __syncthreads();

    float acc[2][4][4] = {};
    mma_chunk(As, Bs, wm, wn, gid, tig, acc);
    gemm_epi(acc, bias, bm, bn, wm, wn, gid, tig, 1, 1, nullptr, 0, h1, 512);
}

// ---- weight split role ---------------------------------------------------------
__device__ void split_role(int local, const float* __restrict__ W, int K, int N,
                           int Kpad, __half* __restrict__ o)
{
    int idx = local * 256 + threadIdx.x;
    if (idx >= N * Kpad) return;
    int n = idx / Kpad, k = idx - n * Kpad;
    float v = (k < K) ? W[(size_t)k * N + n] : 0.f;
    o[idx] = __float2half_rn(v);
}

// ---- gather role: 8 warp-tasks per 256-thread block ----------------------------
__device__ void gather_role(long long task0, const void* __restrict__ idx_raw,
    const float* __restrict__ tables, float* __restrict__ feats)
{
    const int warp = threadIdx.x >> 5, lane = threadIdx.x & 31;
    const long long t = task0 + warp;
    const int f = (int)(t / Bsz), b = (int)(t % Bsz);

    const long long* p64 = (const long long*)idx_raw;
    long long v0 = p64[0], v1 = p64[123], v2 = p64[4567], v3 = p64[89012];
    const bool is64 = (v0 >= 0 && v0 < Nrows) && (v1 >= 0 && v1 < Nrows) &&
                      (v2 >= 0 && v2 < Nrows) && (v3 >= 0 && v3 < Nrows);
    const int* p32 = (const int*)idx_raw;
    const long long base = (long long)f * Bsz * Lk + (long long)b * Lk;

    float2 acc = make_float2(0.f, 0.f);
    #pragma unroll
    for (int l = 0; l < Lk; l++) {
        long long row = is64 ? p64[base + l] : (long long)p32[base + l];
        float2 v = *(const float2*)(tables + ((long long)f * Nrows + row) * Dim + lane * 2);
        acc.x += v.x; acc.y += v.y;
    }
    *(float2*)(feats + (size_t)b * (NFEAT * Dim) + (f + 1) * Dim + lane * 2) = acc;
}

// ---------------- phase kernels (overlap gather with bottom MLP) ---------------
__global__ __launch_bounds__(256)
void phase_a(const float* dense, const float* W0, const float* b0b, __half* h1,
             const float* W1, __half* w1, const float* W2, __half* w2,
             const float* T0, __half* t0, const float* T1, __half* t1,
             const void* idx, const float* tables, float* feats)
{
    __shared__ __align__(16) __half sm[2 * 7680];
    int blk = blockIdx.x;
    if (blk < NSPL) {
        if (blk < 512)       split_role(blk,        W1, 512, 256, 512,  w1);
        else if (blk < 576)  split_role(blk - 512,  W2, 256, 64,  256,  w2);
        else if (blk < 1408) split_role(blk - 576,  T0, 415, 512, YSTR, t0);
        else                 split_role(blk - 1408, T1, 512, 256, 512,  t1);
        return;
    }
    blk -= NSPL;
    if (blk < NB0) { b0_role(sm, blk, dense, W0, b0b, h1); return; }
    blk -= NB0;
    gather_role((long long)blk * 8, idx, tables, feats);
}

__global__ __launch_bounds__(256)
void phase_b(const __half* h1, const __half* w1, const float* b1b, __half* h2,
             const void* idx, const float* tables, float* feats)
{
    __shared__ __align__(16) __half sm[2 * 7680];
    int blk = blockIdx.x;
    if (blk < 512) {
        gemm_core(sm, h1, w1, b1b, 512, blk & 3, blk >> 2, h2, 256);
        return;
    }
    gather_role(GA_TASKS + (long long)(blk - 512) * 8, idx, tables, feats);
}

// ======= standalone t0/t1 GEMM ================================================
__global__ __launch_bounds__(256)
void k_gemm(const __half* __restrict__ A, const __half* __restrict__ B,
            const float* __restrict__ bias, int K, __half* __restrict__ Ch,
            int ldch)
{
    __shared__ __align__(16) __half sm[2 * 7680];
    gemm_core(sm, A, B, bias, K, blockIdx.x, blockIdx.y, Ch, ldch);
}

// ======= b2: CTA 64x64 (128 thr, warps 2x2), K=256, fp32 out into feats =======
__global__ __launch_bounds__(128)
void k_b2(const __half* __restrict__ A, const __half* __restrict__ B,
          const float* __restrict__ bias, float* __restrict__ Cf)
{
    __shared__ __align__(16) __half sm[2][5120];

    const int tid = threadIdx.x, warp = tid >> 5, lane = tid & 31;
    const int wm = warp & 1, wn = warp >> 1;
    const int gid = lane >> 2, tig = lane & 3;
    const int bm = blockIdx.x * 64, bn = 0;
    const int K = 256;

    float acc[2][4][4] = {};
    uint4 pa[2], pb[2];

    auto prefetch = [&](int it) {
        const int k0 = it * 32;
        #pragma unroll
        for (int s = 0; s < 2; s++) {
            int idx = tid + s * 128;
            int r = idx >> 2, kq = idx & 3;
            pa[s] = *(const uint4*)(A + (size_t)(bm + r) * K + k0 + kq * 8);
            pb[s] = *(const uint4*)(B + (size_t)r * K + k0 + kq * 8);
        }
    };

    prefetch(0);
    for (int it = 0; it < 8; it++) {
        __half* As = sm[it & 1];
        __half* Bs = sm[it & 1] + 2560;
        #pragma unroll
        for (int s = 0; s < 2; s++) {
            int idx = tid + s * 128;
            int r = idx >> 2, kq = idx & 3;
            *(uint4*)&As[r * LDA + kq * 8] = pa[s];
            *(uint4*)&Bs[r * LDA + kq * 8] = pb[s];
        }
        __syncthreads();
        if (it + 1 < 8) prefetch(it + 1);
        mma_chunk(As, Bs, wm, wn, gid, tig, acc);
    }
    gemm_epi(acc, bias, bm, bn, wm, wn, gid, tig, 1, 0,
             Cf, NFEAT * Dim, nullptr, 0);
}

// ======= tensor-core interaction: 1 warp per sample (3-term gram) ==============
__global__ __launch_bounds__(128)
void interact_mma(const float* __restrict__ feats, __half* __restrict__ y)
{
    __shared__ __half sF[4][2][32 * ILD];
    const int warp = threadIdx.x >> 5, lane = threadIdx.x & 31;
    const int b = blockIdx.x * 4 + warp;
    const int gid = lane >> 2, tig = lane & 3;
    __half* Fh = &sF[warp][0][0];
    __half* Fl = &sF[warp][1][0];
    const float* fr = feats + (size_t)b * (NFEAT * Dim);

    #pragma unroll
    for (int s = 0; s < 32; s++) {
        int idx = lane + s * 32;
        int r = idx >> 5, cp = (idx & 31) * 2;
        float2 v = (r < NFEAT) ? *(const float2*)(fr + r * 64 + cp)
                               : make_float2(0.f, 0.f);
        __half2 h = __floats2half2_rn(v.x, v.y);
        float2 hd = __half22float2(h);
        __half2 l = __floats2half2_rn(v.x - hd.x, v.y - hd.y);
        *(__half2*)&Fh[r * ILD + cp] = h;
        *(__half2*)&Fl[r * ILD + cp] = l;
    }
    __syncwarp();

    float acc[2][4][4] = {};
    #pragma unroll
    for (int ks = 0; ks < 64; ks += 16) {
        uint32_t ah[2][4], al[2][4], bh[4][2], bl[4][2];
        #pragma unroll
        for (int mt = 0; mt < 2; mt++) {
            int r0 = (mt * 16 + gid) * ILD + ks + 2 * tig;
            ah[mt][0] = *(const uint32_t*)&Fh[r0];
            ah[mt][1] = *(const uint32_t*)&Fh[r0 + 8 * ILD];
            ah[mt][2] = *(const uint32_t*)&Fh[r0 + 8];
            ah[mt][3] = *(const uint32_t*)&Fh[r0 + 8 * ILD + 8];
            al[mt][0] = *(const uint32_t*)&Fl[r0];
            al[mt][1] = *(const uint32_t*)&Fl[r0 + 8 * ILD];
            al[mt][2] = *(const uint32_t*)&Fl[r0 + 8];
            al[mt][3] = *(const uint32_t*)&Fl[r0 + 8 * ILD + 8];
        }
        #pragma unroll
        for (int nt = 0; nt < 4; nt++) {
            int n0 = (nt * 8 + gid) * ILD + ks + 2 * tig;
            bh[nt][0] = *(const uint32_t*)&Fh[n0];
            bh[nt][1] = *(const uint32_t*)&Fh[n0 + 8];
            bl[nt][0] = *(const uint32_t*)&Fl[n0];
            bl[nt][1] = *(const uint32_t*)&Fl[n0 + 8];
        }
        #pragma unroll
        for (int mt = 0; mt < 2; mt++)
            #pragma unroll
            for (int nt = 0; nt < 4; nt++) {
                MMA_F16(acc[mt][nt], ah[mt], bh[nt][0], bh[nt][1]);
                MMA_F16(acc[mt][nt], ah[mt], bl[nt][0], bl[nt][1]);
                MMA_F16(acc[mt][nt], al[mt], bh[nt][0], bh[nt][1]);
            }
    }

    __half* yr = y + (size_t)b * YSTR;
    #pragma unroll
    for (int s = 0; s < 2; s++) yr[lane + s * 32] = Fh[lane + s * 32];
    if (lane == 0) yr[OVERIN] = __float2half_rn(0.f);

    #pragma unroll
    for (int mt = 0; mt < 2; mt++)
        #pragma unroll
        for (int nt = 0; nt < 4; nt++)
            #pragma unroll
            for (int e = 0; e < 4; e++) {
                int m = mt * 16 + gid + (e >> 1) * 8;
                int n = nt * 8 + tig * 2 + (e & 1);
                if (n > m && n < NFEAT) {
                    int p = m * (2 * NFEAT - m - 1) / 2 + (n - m - 1);
                    yr[Dim + p] = __float2half_rn(acc[mt][nt][e]);
                }
            }
}

// ======= final layer ============================================================
__global__ __launch_bounds__(256)
void gemv_final(const __half* __restrict__ X, const float* __restrict__ w,
                const float* __restrict__ bias, float* __restrict__ out)
{
    const int row = (blockIdx.x * blockDim.x + threadIdx.x) >> 5;
    const int lane = threadIdx.x & 31;
    if (row >= Bsz) return;
    uint4 hv = *(const uint4*)(X + (size_t)row * 256 + lane * 8);
    const __half2* hp = (const __half2*)&hv;
    float s = 0.f;
    #pragma unroll
    for (int q = 0; q < 4; q++) {
        float2 h2 = __half22float2(hp[q]);
        s = fmaf(h2.x, w[lane * 8 + q * 2], s);
        s = fmaf(h2.y, w[lane * 8 + q * 2 + 1], s);
    }
    #pragma unroll
    for (int o = 16; o; o >>= 1) s += __shfl_down_sync(0xffffffffu, s, o);
    if (lane == 0) out[row] = s + bias[0];
}

// -----------------------------------------------------------------------------
static void* sym_addr(const void* sym)
{
    void* p = nullptr;
    cudaGetSymbolAddress(&p, sym);
    return p;
}

extern "C" void kernel_launch(void* const* d_in, const int* in_sizes, int n_in,
                              void* d_out, int out_size)
{
    (void)in_sizes; (void)n_in; (void)out_size;

    const float* dense  = (const float*)d_in[0];
    const void*  sp_idx = d_in[1];
    const float* tables = (const float*)d_in[2];
    const float* botW0 = (const float*)d_in[3],  *botb0 = (const float*)d_in[4];
    const float* botW1 = (const float*)d_in[5],  *botb1 = (const float*)d_in[6];
    const float* botW2 = (const float*)d_in[7],  *botb2 = (const float*)d_in[8];
    const float* topW0 = (const float*)d_in[9],  *topb0 = (const float*)d_in[10];
    const float* topW1 = (const float*)d_in[11], *topb1 = (const float*)d_in[12];
    const float* topW2 = (const float*)d_in[13], *topb2 = (const float*)d_in[14];
    float* out = (float*)d_out;

    float*  feats = (float*)sym_addr(g_feats);
    __half* h1 = (__half*)sym_addr(g_h1);
    __half* h2 = (__half*)sym_addr(g_h2);
    __half* y  = (__half*)sym_addr(g_y);
    __half* w1 = (__half*)sym_addr(g_w1);
    __half* w2 = (__half*)sym_addr(g_w2);
    __half* t0 = (__half*)sym_addr(g_t0);
    __half* t1 = (__half*)sym_addr(g_t1);

    // #1 phase_a (splits + b0 + gather/2), #2 phase_b (b1 + gather/2),
    // #3 b2, #4 interact (profiled), #5 t0, #6 t1, #7 gemv
    phase_a<<<NSPL + NB0 + GA_BLK, 256>>>(dense, botW0, botb0, h1,
        botW1, w1, botW2, w2, topW0, t0, topW1, t1, sp_idx, tables, feats);
    phase_b<<<512 + GB_BLK, 256>>>(h1, w1, botb1, h2, sp_idx, tables, feats);
    k_b2<<<256, 128>>>(h2, w2, botb2, feats);
    interact_mma<<<Bsz / 4, 128>>>(feats, y);
    k_gemm<<<dim3(8, 128), 256>>>(y, t0, topb0, YSTR, h1, 512);
    k_gemm<<<dim3(4, 128), 256>>>(h1, t1, topb1, 512, h2, 256);
    gemv_final<<<(Bsz * 32) / 256, 256>>>(h2, topW2, topb2, out);
}

// round 14
// speedup vs baseline: 1.4047x; 1.4047x over previous
#include <cuda_runtime.h>
#include <cuda_fp16.h>
#include <cstdint>

#define Bsz 16384
#define Fn 26
#define Nrows 100000
#define Dim 64
#define Lk 4
#define NFEAT 27
#define NPAIRS 351
#define OVERIN 415
#define YSTR 416
#define LDA 40
#define ILD 72

// ---------------- scratch -----------------------------------------------------
__device__ float  g_feats[(size_t)Bsz * NFEAT * Dim];
__device__ __half g_h1[(size_t)Bsz * 512];
__device__ __half g_h2[(size_t)Bsz * 256];
__device__ __half g_y[(size_t)Bsz * YSTR];
__device__ __half g_w1[256 * 512];
__device__ __half g_w2[64 * 256];
__device__ __half g_t0[512 * YSTR];
__device__ __half g_t1[256 * 512];

#define MMA_F16(c, a, b0v, b1v) \
    asm volatile("mma.sync.aligned.m16n8k16.row.col.f32.f16.f16.f32 " \
        "{%0,%1,%2,%3}, {%4,%5,%6,%7}, {%8,%9}, {%0,%1,%2,%3};" \
        : "+f"((c)[0]), "+f"((c)[1]), "+f"((c)[2]), "+f"((c)[3]) \
        : "r"((a)[0]), "r"((a)[1]), "r"((a)[2]), "r"((a)[3]), "r"(b0v), "r"(b1v))

#define CP16(dst, src) \
    asm volatile("cp.async.cg.shared.global [%0], [%1], 16;" \
        :: "r"(dst), "l"(src))
#define CP_COMMIT() asm volatile("cp.async.commit_group;" ::: "memory")
#define CP_WAIT1()  asm volatile("cp.async.wait_group 1;" ::: "memory")
#define CP_WAIT0()  asm volatile("cp.async.wait_group 0;" ::: "memory")

__device__ __forceinline__ uint32_t smem_u32(const void* p) {
    uint32_t a;
    asm("{ .reg .u64 t; cvta.to.shared.u64 t, %1; cvt.u32.u64 %0, t; }"
        : "=r"(a) : "l"(p));
    return a;
}

// ---- 32-K mma chunk: As rows x LDA, Bs[64][LDA], scalar frag loads -----------
__device__ __forceinline__ void mma_chunk(const __half* As, const __half* Bs,
    int wm, int wn, int gid, int tig, float acc[2][4][4])
{
    #pragma unroll
    for (int ks = 0; ks < 32; ks += 16) {
        uint32_t a[2][4], bh[4][2];
        #pragma unroll
        for (int mt = 0; mt < 2; mt++) {
            int r0 = (wm * 32 + mt * 16 + gid) * LDA + ks + 2 * tig;
            a[mt][0] = *(const uint32_t*)&As[r0];
            a[mt][1] = *(const uint32_t*)&As[r0 + 8 * LDA];
            a[mt][2] = *(const uint32_t*)&As[r0 + 8];
            a[mt][3] = *(const uint32_t*)&As[r0 + 8 * LDA + 8];
        }
        #pragma unroll
        for (int nt = 0; nt < 4; nt++) {
            int n0 = (wn * 32 + nt * 8 + gid) * LDA + ks + 2 * tig;
            bh[nt][0] = *(const uint32_t*)&Bs[n0];
            bh[nt][1] = *(const uint32_t*)&Bs[n0 + 8];
        }
        #pragma unroll
        for (int mt = 0; mt < 2; mt++)
            #pragma unroll
            for (int nt = 0; nt < 4; nt++)
                MMA_F16(acc[mt][nt], a[mt], bh[nt][0], bh[nt][1]);
    }
}

__device__ __forceinline__ void gemm_epi(float acc[2][4][4],
    const float* __restrict__ bias, int bm, int bn, int wm, int wn,
    int gid, int tig, int relu, int outmode,
    float* __restrict__ Cf, int ldcf, __half* __restrict__ Ch, int ldch)
{
    #pragma unroll
    for (int mt = 0; mt < 2; mt++) {
        int r0 = bm + wm * 32 + mt * 16 + gid;
        #pragma unroll
        for (int nt = 0; nt < 4; nt++) {
            int cc = bn + wn * 32 + nt * 8 + tig * 2;
            float b0 = bias[cc], b1 = bias[cc + 1];
            float v00 = acc[mt][nt][0] + b0, v01 = acc[mt][nt][1] + b1;
            float v10 = acc[mt][nt][2] + b0, v11 = acc[mt][nt][3] + b1;
            if (relu) {
                v00 = fmaxf(v00, 0.f); v01 = fmaxf(v01, 0.f);
                v10 = fmaxf(v10, 0.f); v11 = fmaxf(v11, 0.f);
            }
            if (outmode == 0) {
                *(float2*)&Cf[(size_t)r0 * ldcf + cc]       = make_float2(v00, v01);
                *(float2*)&Cf[(size_t)(r0 + 8) * ldcf + cc] = make_float2(v10, v11);
            } else {
                *(__half2*)&Ch[(size_t)r0 * ldch + cc]       = __floats2half2_rn(v00, v01);
                *(__half2*)&Ch[(size_t)(r0 + 8) * ldch + cc] = __floats2half2_rn(v10, v11);
            }
        }
    }
}

// ======= main GEMM: CTA 128x64, 3-stage cp.async pipeline, 1 sync / K-iter ====
__global__ __launch_bounds__(256)
void k_gemm(const __half* __restrict__ A, const __half* __restrict__ B,
            const float* __restrict__ bias, int K, __half* __restrict__ Ch,
            int ldch)
{
    __shared__ __align__(16) __half sm[3 * 7680];   // 3 stages x 15360 B

    const int tid = threadIdx.x, warp = tid >> 5, lane = tid & 31;
    const int wm = warp & 3, wn = warp >> 2;
    const int gid = lane >> 2, tig = lane & 3;
    const int bm = blockIdx.y * 128, bn = blockIdx.x * 64;
    const uint32_t sb = smem_u32(sm);

    float acc[2][4][4] = {};
    const int kIter = K >> 5;

    const int rA = tid >> 2, kqA = tid & 3;         // A: 2 cp16 per thread
    auto issue = [&](int it) {
        const int k0 = it * 32;
        const uint32_t base = sb + (uint32_t)((it % 3) * 15360);
        CP16(base + rA * 80 + kqA * 16,
             A + (size_t)(bm + rA) * K + k0 + kqA * 8);
        CP16(base + (rA + 64) * 80 + kqA * 16,
             A + (size_t)(bm + rA + 64) * K + k0 + kqA * 8);
        CP16(base + 10240 + rA * 80 + kqA * 16,
             B + (size_t)(bn + rA) * K + k0 + kqA * 8);
        CP_COMMIT();
    };

    issue(0);
    if (kIter > 1) issue(1);
    for (int it = 0; it < kIter; it++) {
        if (it + 2 <= kIter) { CP_WAIT1(); } else { CP_WAIT0(); }
        __syncthreads();
        if (it + 2 < kIter) issue(it + 2);
        __half* As = sm + (it % 3) * 7680;
        __half* Bs = As + 5120;
        mma_chunk(As, Bs, wm, wn, gid, tig, acc);
    }
    gemm_epi(acc, bias, bm, bn, wm, wn, gid, tig, 1, 1, nullptr, 0, Ch, ldch);
}

// ======= b2: CTA 64x64 (128 thr, warps 2x2), K=256, fp32 out into feats =======
__global__ __launch_bounds__(128)
void k_b2(const __half* __restrict__ A, const __half* __restrict__ B,
          const float* __restrict__ bias, float* __restrict__ Cf)
{
    __shared__ __align__(16) __half sm[2][5120];

    const int tid = threadIdx.x, warp = tid >> 5, lane = tid & 31;
    const int wm = warp & 1, wn = warp >> 1;
    const int gid = lane >> 2, tig = lane & 3;
    const int bm = blockIdx.x * 64, bn = 0;
    const int K = 256;

    float acc[2][4][4] = {};
    uint4 pa[2], pb[2];

    auto prefetch = [&](int it) {
        const int k0 = it * 32;
        #pragma unroll
        for (int s = 0; s < 2; s++) {
            int idx = tid + s * 128;
            int r = idx >> 2, kq = idx & 3;
            pa[s] = *(const uint4*)(A + (size_t)(bm + r) * K + k0 + kq * 8);
            pb[s] = *(const uint4*)(B + (size_t)r * K + k0 + kq * 8);
        }
    };

    prefetch(0);
    for (int it = 0; it < 8; it++) {
        __half* As = sm[it & 1];
        __half* Bs = sm[it & 1] + 2560;
        #pragma unroll
        for (int s = 0; s < 2; s++) {
            int idx = tid + s * 128;
            int r = idx >> 2, kq = idx & 3;
            *(uint4*)&As[r * LDA + kq * 8] = pa[s];
            *(uint4*)&Bs[r * LDA + kq * 8] = pb[s];
        }
        __syncthreads();
        if (it + 1 < 8) prefetch(it + 1);
        mma_chunk(As, Bs, wm, wn, gid, tig, acc);
    }
    gemm_epi(acc, bias, bm, bn, wm, wn, gid, tig, 1, 0,
             Cf, NFEAT * Dim, nullptr, 0);
}

// ======= b0: K=32 (13 real), fp32 inputs converted inline ======================
__global__ __launch_bounds__(256)
void k_b0(const float* __restrict__ dense, const float* __restrict__ W0,
          const float* __restrict__ bias, __half* __restrict__ h1)
{
    __shared__ __align__(16) __half sm[7680];
    __half* As = sm;
    __half* Bs = sm + 5120;
    const int tid = threadIdx.x, warp = tid >> 5, lane = tid & 31;
    const int wm = warp & 3, wn = warp >> 2;
    const int gid = lane >> 2, tig = lane & 3;
    const int bm = blockIdx.y * 128, bn = blockIdx.x * 64;

    #pragma unroll
    for (int s = 0; s < 8; s++) {
        int idx = tid + s * 256;
        int r = idx >> 4, cp = (idx & 15) * 2;
        float x0 = (cp < 13)     ? dense[(size_t)(bm + r) * 13 + cp]     : 0.f;
        float x1 = (cp + 1 < 13) ? dense[(size_t)(bm + r) * 13 + cp + 1] : 0.f;
        *(__half2*)&As[r * LDA + cp] = __floats2half2_rn(x0, x1);
    }
    #pragma unroll
    for (int s = 0; s < 8; s++) {
        int idx = tid + s * 256;
        int n = idx & 63, k = idx >> 6;
        float v = (k < 13) ? W0[(size_t)k * 512 + bn + n] : 0.f;
        Bs[n * LDA + k] = __float2half_rn(v);
    }
    __syncthreads();

    float acc[2][4][4] = {};
    mma_chunk(As, Bs, wm, wn, gid, tig, acc);
    gemm_epi(acc, bias, bm, bn, wm, wn, gid, tig, 1, 1, nullptr, 0, h1, 512);
}

// ======= all weight splits in one launch (block-role) ==========================
__device__ void split_role(int local, const float* __restrict__ W, int K, int N,
                           int Kpad, __half* __restrict__ o)
{
    int idx = local * 256 + threadIdx.x;
    if (idx >= N * Kpad) return;
    int n = idx / Kpad, k = idx - n * Kpad;
    float v = (k < K) ? W[(size_t)k * N + n] : 0.f;
    o[idx] = __float2half_rn(v);
}

__global__ __launch_bounds__(256)
void k_split(const float* W1, __half* w1, const float* W2, __half* w2,
             const float* T0, __half* t0, const float* T1, __half* t1)
{
    int blk = blockIdx.x;
    if (blk < 512)       split_role(blk,        W1, 512, 256, 512,  w1);
    else if (blk < 576)  split_role(blk - 512,  W2, 256, 64,  256,  w2);
    else if (blk < 1408) split_role(blk - 576,  T0, 415, 512, YSTR, t0);
    else                 split_role(blk - 1408, T1, 512, 256, 512,  t1);
}

// ======= embedding gather + pool: one warp per (f, b) ==========================
__global__ __launch_bounds__(256)
void k_gather(const void* __restrict__ idx_raw,
              const float* __restrict__ tables, float* __restrict__ feats)
{
    const int gwarp = (blockIdx.x * blockDim.x + threadIdx.x) >> 5;
    const int lane = threadIdx.x & 31;
    const int f = gwarp / Bsz, b = gwarp % Bsz;

    const long long* p64 = (const long long*)idx_raw;
    long long v0 = p64[0], v1 = p64[123], v2 = p64[4567], v3 = p64[89012];
    const bool is64 = (v0 >= 0 && v0 < Nrows) && (v1 >= 0 && v1 < Nrows) &&
                      (v2 >= 0 && v2 < Nrows) && (v3 >= 0 && v3 < Nrows);
    const int* p32 = (const int*)idx_raw;
    const long long base = (long long)f * Bsz * Lk + (long long)b * Lk;

    float2 acc = make_float2(0.f, 0.f);
    #pragma unroll
    for (int l = 0; l < Lk; l++) {
        long long row = is64 ? p64[base + l] : (long long)p32[base + l];
        float2 v = *(const float2*)(tables + ((long long)f * Nrows + row) * Dim + lane * 2);
        acc.x += v.x; acc.y += v.y;
    }
    *(float2*)(feats + (size_t)b * (NFEAT * Dim) + (f + 1) * Dim + lane * 2) = acc;
}

// ======= tensor-core interaction: 1 warp per sample (3-term gram) ==============
__global__ __launch_bounds__(128)
void interact_mma(const float* __restrict__ feats, __half* __restrict__ y)
{
    __shared__ __half sF[4][2][32 * ILD];
    const int warp = threadIdx.x >> 5, lane = threadIdx.x & 31;
    const int b = blockIdx.x * 4 + warp;
    const int gid = lane >> 2, tig = lane & 3;
    __half* Fh = &sF[warp][0][0];
    __half* Fl = &sF[warp][1][0];
    const float* fr = feats + (size_t)b * (NFEAT * Dim);

    #pragma unroll
    for (int s = 0; s < 32; s++) {
        int idx = lane + s * 32;
        int r = idx >> 5, cp = (idx & 31) * 2;
        float2 v = (r < NFEAT) ? *(const float2*)(fr + r * 64 + cp)
                               : make_float2(0.f, 0.f);
        __half2 h = __floats2half2_rn(v.x, v.y);
        float2 hd = __half22float2(h);
        __half2 l = __floats2half2_rn(v.x - hd.x, v.y - hd.y);
        *(__half2*)&Fh[r * ILD + cp] = h;
        *(__half2*)&Fl[r * ILD + cp] = l;
    }
    __syncwarp();

    float acc[2][4][4] = {};
    #pragma unroll
    for (int ks = 0; ks < 64; ks += 16) {
        uint32_t ah[2][4], al[2][4], bh[4][2], bl[4][2];
        #pragma unroll
        for (int mt = 0; mt < 2; mt++) {
            int r0 = (mt * 16 + gid) * ILD + ks + 2 * tig;
            ah[mt][0] = *(const uint32_t*)&Fh[r0];
            ah[mt][1] = *(const uint32_t*)&Fh[r0 + 8 * ILD];
            ah[mt][2] = *(const uint32_t*)&Fh[r0 + 8];
            ah[mt][3] = *(const uint32_t*)&Fh[r0 + 8 * ILD + 8];
            al[mt][0] = *(const uint32_t*)&Fl[r0];
            al[mt][1] = *(const uint32_t*)&Fl[r0 + 8 * ILD];
            al[mt][2] = *(const uint32_t*)&Fl[r0 + 8];
            al[mt][3] = *(const uint32_t*)&Fl[r0 + 8 * ILD + 8];
        }
        #pragma unroll
        for (int nt = 0; nt < 4; nt++) {
            int n0 = (nt * 8 + gid) * ILD + ks + 2 * tig;
            bh[nt][0] = *(const uint32_t*)&Fh[n0];
            bh[nt][1] = *(const uint32_t*)&Fh[n0 + 8];
            bl[nt][0] = *(const uint32_t*)&Fl[n0];
            bl[nt][1] = *(const uint32_t*)&Fl[n0 + 8];
        }
        #pragma unroll
        for (int mt = 0; mt < 2; mt++)
            #pragma unroll
            for (int nt = 0; nt < 4; nt++) {
                MMA_F16(acc[mt][nt], ah[mt], bh[nt][0], bh[nt][1]);
                MMA_F16(acc[mt][nt], ah[mt], bl[nt][0], bl[nt][1]);
                MMA_F16(acc[mt][nt], al[mt], bh[nt][0], bh[nt][1]);
            }
    }

    __half* yr = y + (size_t)b * YSTR;
    #pragma unroll
    for (int s = 0; s < 2; s++) yr[lane + s * 32] = Fh[lane + s * 32];
    if (lane == 0) yr[OVERIN] = __float2half_rn(0.f);

    #pragma unroll
    for (int mt = 0; mt < 2; mt++)
        #pragma unroll
        for (int nt = 0; nt < 4; nt++)
            #pragma unroll
            for (int e = 0; e < 4; e++) {
                int m = mt * 16 + gid + (e >> 1) * 8;
                int n = nt * 8 + tig * 2 + (e & 1);
                if (n > m && n < NFEAT) {
                    int p = m * (2 * NFEAT - m - 1) / 2 + (n - m - 1);
                    yr[Dim + p] = __float2half_rn(acc[mt][nt][e]);
                }
            }
}

// ======= final layer ============================================================
__global__ __launch_bounds__(256)
void gemv_final(const __half* __restrict__ X, const float* __restrict__ w,
                const float* __restrict__ bias, float* __restrict__ out)
{
    const int row = (blockIdx.x * blockDim.x + threadIdx.x) >> 5;
    const int lane = threadIdx.x & 31;
    if (row >= Bsz) return;
    uint4 hv = *(const uint4*)(X + (size_t)row * 256 + lane * 8);
    const __half2* hp = (const __half2*)&hv;
    float s = 0.f;
    #pragma unroll
    for (int q = 0; q < 4; q++) {
        float2 h2 = __half22float2(hp[q]);
        s = fmaf(h2.x, w[lane * 8 + q * 2], s);
        s = fmaf(h2.y, w[lane * 8 + q * 2 + 1], s);
    }
    #pragma unroll
    for (int o = 16; o; o >>= 1) s += __shfl_down_sync(0xffffffffu, s, o);
    if (lane == 0) out[row] = s + bias[0];
}

// -----------------------------------------------------------------------------
static void* sym_addr(const void* sym)
{
    void* p = nullptr;
    cudaGetSymbolAddress(&p, sym);
    return p;
}

extern "C" void kernel_launch(void* const* d_in, const int* in_sizes, int n_in,
                              void* d_out, int out_size)
{
    (void)in_sizes; (void)n_in; (void)out_size;

    const float* dense  = (const float*)d_in[0];
    const void*  sp_idx = d_in[1];
    const float* tables = (const float*)d_in[2];
    const float* botW0 = (const float*)d_in[3],  *botb0 = (const float*)d_in[4];
    const float* botW1 = (const float*)d_in[5],  *botb1 = (const float*)d_in[6];
    const float* botW2 = (const float*)d_in[7],  *botb2 = (const float*)d_in[8];
    const float* topW0 = (const float*)d_in[9],  *topb0 = (const float*)d_in[10];
    const float* topW1 = (const float*)d_in[11], *topb1 = (const float*)d_in[12];
    const float* topW2 = (const float*)d_in[13], *topb2 = (const float*)d_in[14];
    float* out = (float*)d_out;

    float*  feats = (float*)sym_addr(g_feats);
    __half* h1 = (__half*)sym_addr(g_h1);
    __half* h2 = (__half*)sym_addr(g_h2);
    __half* y  = (__half*)sym_addr(g_y);
    __half* w1 = (__half*)sym_addr(g_w1);
    __half* w2 = (__half*)sym_addr(g_w2);
    __half* t0 = (__half*)sym_addr(g_t0);
    __half* t1 = (__half*)sym_addr(g_t1);

    // #1 splits, #2 b0, #3 gather, #4 b1 (profiled), #5 b2, #6 interact,
    // #7 t0, #8 t1, #9 gemv
    k_split<<<1920, 256>>>(botW1, w1, botW2, w2, topW0, t0, topW1, t1);
    k_b0<<<dim3(8, 128), 256>>>(dense, botW0, botb0, h1);
    k_gather<<<(Fn * Bsz * 32) / 256, 256>>>(sp_idx, tables, feats);
    k_gemm<<<dim3(4, 128), 256>>>(h1, w1, botb1, 512, h2, 256);
    k_b2<<<256, 128>>>(h2, w2, botb2, feats);
    interact_mma<<<Bsz / 4, 128>>>(feats, y);
    k_gemm<<<dim3(8, 128), 256>>>(y, t0, topb0, YSTR, h1, 512);
    k_gemm<<<dim3(4, 128), 256>>>(h1, t1, topb1, 512, h2, 256);
    gemv_final<<<(Bsz * 32) / 256, 256>>>(h2, topW2, topb2, out);
}

// round 15
// speedup vs baseline: 1.5164x; 1.0795x over previous
#include <cuda_runtime.h>
#include <cuda_fp16.h>
#include <cstdint>

#define Bsz 16384
#define Fn 26
#define Nrows 100000
#define Dim 64
#define Lk 4
#define NFEAT 27
#define NPAIRS 351
#define OVERIN 415
#define YSTR 416
#define LDA 40
#define ILD 72

// ---------------- scratch -----------------------------------------------------
__device__ float  g_feats[(size_t)Bsz * NFEAT * Dim];
__device__ __half g_h1[(size_t)Bsz * 512];
__device__ __half g_h2[(size_t)Bsz * 256];
__device__ __half g_y[(size_t)Bsz * YSTR];
__device__ __half g_w1[256 * 512];
__device__ __half g_w2[64 * 256];
__device__ __half g_t0[512 * YSTR];
__device__ __half g_t1[256 * 512];

#define MMA_F16(c, a, b0v, b1v) \
    asm volatile("mma.sync.aligned.m16n8k16.row.col.f32.f16.f16.f32 " \
        "{%0,%1,%2,%3}, {%4,%5,%6,%7}, {%8,%9}, {%0,%1,%2,%3};" \
        : "+f"((c)[0]), "+f"((c)[1]), "+f"((c)[2]), "+f"((c)[3]) \
        : "r"((a)[0]), "r"((a)[1]), "r"((a)[2]), "r"((a)[3]), "r"(b0v), "r"(b1v))

#define CP16(dst, src) \
    asm volatile("cp.async.cg.shared.global [%0], [%1], 16;" \
        :: "r"(dst), "l"(src))
#define CP_COMMIT() asm volatile("cp.async.commit_group;" ::: "memory")
#define CP_WAIT1()  asm volatile("cp.async.wait_group 1;" ::: "memory")
#define CP_WAIT0()  asm volatile("cp.async.wait_group 0;" ::: "memory")

__device__ __forceinline__ uint32_t smem_u32(const void* p) {
    uint32_t a;
    asm("{ .reg .u64 t; cvta.to.shared.u64 t, %1; cvt.u32.u64 %0, t; }"
        : "=r"(a) : "l"(p));
    return a;
}

// ---- 32-K mma chunk: As rows x LDA, Bs[64][LDA], scalar frag loads -----------
__device__ __forceinline__ void mma_chunk(const __half* As, const __half* Bs,
    int wm, int wn, int gid, int tig, float acc[2][4][4])
{
    #pragma unroll
    for (int ks = 0; ks < 32; ks += 16) {
        uint32_t a[2][4], bh[4][2];
        #pragma unroll
        for (int mt = 0; mt < 2; mt++) {
            int r0 = (wm * 32 + mt * 16 + gid) * LDA + ks + 2 * tig;
            a[mt][0] = *(const uint32_t*)&As[r0];
            a[mt][1] = *(const uint32_t*)&As[r0 + 8 * LDA];
            a[mt][2] = *(const uint32_t*)&As[r0 + 8];
            a[mt][3] = *(const uint32_t*)&As[r0 + 8 * LDA + 8];
        }
        #pragma unroll
        for (int nt = 0; nt < 4; nt++) {
            int n0 = (wn * 32 + nt * 8 + gid) * LDA + ks + 2 * tig;
            bh[nt][0] = *(const uint32_t*)&Bs[n0];
            bh[nt][1] = *(const uint32_t*)&Bs[n0 + 8];
        }
        #pragma unroll
        for (int mt = 0; mt < 2; mt++)
            #pragma unroll
            for (int nt = 0; nt < 4; nt++)
                MMA_F16(acc[mt][nt], a[mt], bh[nt][0], bh[nt][1]);
    }
}

__device__ __forceinline__ void gemm_epi(float acc[2][4][4],
    const float* __restrict__ bias, int bm, int bn, int wm, int wn,
    int gid, int tig, int relu, int outmode,
    float* __restrict__ Cf, int ldcf, __half* __restrict__ Ch, int ldch)
{
    #pragma unroll
    for (int mt = 0; mt < 2; mt++) {
        int r0 = bm + wm * 32 + mt * 16 + gid;
        #pragma unroll
        for (int nt = 0; nt < 4; nt++) {
            int cc = bn + wn * 32 + nt * 8 + tig * 2;
            float b0 = bias[cc], b1 = bias[cc + 1];
            float v00 = acc[mt][nt][0] + b0, v01 = acc[mt][nt][1] + b1;
            float v10 = acc[mt][nt][2] + b0, v11 = acc[mt][nt][3] + b1;
            if (relu) {
                v00 = fmaxf(v00, 0.f); v01 = fmaxf(v01, 0.f);
                v10 = fmaxf(v10, 0.f); v11 = fmaxf(v11, 0.f);
            }
            if (outmode == 0) {
                *(float2*)&Cf[(size_t)r0 * ldcf + cc]       = make_float2(v00, v01);
                *(float2*)&Cf[(size_t)(r0 + 8) * ldcf + cc] = make_float2(v10, v11);
            } else {
                *(__half2*)&Ch[(size_t)r0 * ldch + cc]       = __floats2half2_rn(v00, v01);
                *(__half2*)&Ch[(size_t)(r0 + 8) * ldch + cc] = __floats2half2_rn(v10, v11);
            }
        }
    }
}

// ======= main GEMM: CTA 128x64, 3-stage cp.async pipeline, 1 sync / K-iter ====
__global__ __launch_bounds__(256)
void k_gemm(const __half* __restrict__ A, const __half* __restrict__ B,
            const float* __restrict__ bias, int K, __half* __restrict__ Ch,
            int ldch)
{
    __shared__ __align__(16) __half sm[3 * 7680];   // 3 stages x 15360 B

    const int tid = threadIdx.x, warp = tid >> 5, lane = tid & 31;
    const int wm = warp & 3, wn = warp >> 2;
    const int gid = lane >> 2, tig = lane & 3;
    const int bm = blockIdx.y * 128, bn = blockIdx.x * 64;
    const uint32_t sb = smem_u32(sm);

    float acc[2][4][4] = {};
    const int kIter = K >> 5;

    const int rA = tid >> 2, kqA = tid & 3;
    auto issue = [&](int it) {
        const int k0 = it * 32;
        const uint32_t base = sb + (uint32_t)((it % 3) * 15360);
        CP16(base + rA * 80 + kqA * 16,
             A + (size_t)(bm + rA) * K + k0 + kqA * 8);
        CP16(base + (rA + 64) * 80 + kqA * 16,
             A + (size_t)(bm + rA + 64) * K + k0 + kqA * 8);
        CP16(base + 10240 + rA * 80 + kqA * 16,
             B + (size_t)(bn + rA) * K + k0 + kqA * 8);
        CP_COMMIT();
    };

    issue(0);
    if (kIter > 1) issue(1);
    for (int it = 0; it < kIter; it++) {
        if (it + 2 <= kIter) { CP_WAIT1(); } else { CP_WAIT0(); }
        __syncthreads();
        if (it + 2 < kIter) issue(it + 2);
        __half* As = sm + (it % 3) * 7680;
        __half* Bs = As + 5120;
        mma_chunk(As, Bs, wm, wn, gid, tig, acc);
    }
    gemm_epi(acc, bias, bm, bn, wm, wn, gid, tig, 1, 1, nullptr, 0, Ch, ldch);
}

// ======= b2: CTA 64x64 (128 thr, warps 2x2), K=256, fp32 out into feats =======
__global__ __launch_bounds__(128)
void k_b2(const __half* __restrict__ A, const __half* __restrict__ B,
          const float* __restrict__ bias, float* __restrict__ Cf)
{
    __shared__ __align__(16) __half sm[2][5120];

    const int tid = threadIdx.x, warp = tid >> 5, lane = tid & 31;
    const int wm = warp & 1, wn = warp >> 1;
    const int gid = lane >> 2, tig = lane & 3;
    const int bm = blockIdx.x * 64, bn = 0;
    const int K = 256;

    float acc[2][4][4] = {};
    uint4 pa[2], pb[2];

    auto prefetch = [&](int it) {
        const int k0 = it * 32;
        #pragma unroll
        for (int s = 0; s < 2; s++) {
            int idx = tid + s * 128;
            int r = idx >> 2, kq = idx & 3;
            pa[s] = *(const uint4*)(A + (size_t)(bm + r) * K + k0 + kq * 8);
            pb[s] = *(const uint4*)(B + (size_t)r * K + k0 + kq * 8);
        }
    };

    prefetch(0);
    for (int it = 0; it < 8; it++) {
        __half* As = sm[it & 1];
        __half* Bs = sm[it & 1] + 2560;
        #pragma unroll
        for (int s = 0; s < 2; s++) {
            int idx = tid + s * 128;
            int r = idx >> 2, kq = idx & 3;
            *(uint4*)&As[r * LDA + kq * 8] = pa[s];
            *(uint4*)&Bs[r * LDA + kq * 8] = pb[s];
        }
        __syncthreads();
        if (it + 1 < 8) prefetch(it + 1);
        mma_chunk(As, Bs, wm, wn, gid, tig, acc);
    }
    gemm_epi(acc, bias, bm, bn, wm, wn, gid, tig, 1, 0,
             Cf, NFEAT * Dim, nullptr, 0);
}

// ======= b0: K=32 (13 real), fp32 inputs converted inline ======================
__global__ __launch_bounds__(256)
void k_b0(const float* __restrict__ dense, const float* __restrict__ W0,
          const float* __restrict__ bias, __half* __restrict__ h1)
{
    __shared__ __align__(16) __half sm[7680];
    __half* As = sm;
    __half* Bs = sm + 5120;
    const int tid = threadIdx.x, warp = tid >> 5, lane = tid & 31;
    const int wm = warp & 3, wn = warp >> 2;
    const int gid = lane >> 2, tig = lane & 3;
    const int bm = blockIdx.y * 128, bn = blockIdx.x * 64;

    #pragma unroll
    for (int s = 0; s < 8; s++) {
        int idx = tid + s * 256;
        int r = idx >> 4, cp = (idx & 15) * 2;
        float x0 = (cp < 13)     ? dense[(size_t)(bm + r) * 13 + cp]     : 0.f;
        float x1 = (cp + 1 < 13) ? dense[(size_t)(bm + r) * 13 + cp + 1] : 0.f;
        *(__half2*)&As[r * LDA + cp] = __floats2half2_rn(x0, x1);
    }
    #pragma unroll
    for (int s = 0; s < 8; s++) {
        int idx = tid + s * 256;
        int n = idx & 63, k = idx >> 6;
        float v = (k < 13) ? W0[(size_t)k * 512 + bn + n] : 0.f;
        Bs[n * LDA + k] = __float2half_rn(v);
    }
    __syncthreads();

    float acc[2][4][4] = {};
    mma_chunk(As, Bs, wm, wn, gid, tig, acc);
    gemm_epi(acc, bias, bm, bn, wm, wn, gid, tig, 1, 1, nullptr, 0, h1, 512);
}

// ======= all weight splits in one launch ========================================
__device__ void split_role(int local, const float* __restrict__ W, int K, int N,
                           int Kpad, __half* __restrict__ o)
{
    int idx = local * 256 + threadIdx.x;
    if (idx >= N * Kpad) return;
    int n = idx / Kpad, k = idx - n * Kpad;
    float v = (k < K) ? W[(size_t)k * N + n] : 0.f;
    o[idx] = __float2half_rn(v);
}

__global__ __launch_bounds__(256)
void k_split(const float* W1, __half* w1, const float* W2, __half* w2,
             const float* T0, __half* t0, const float* T1, __half* t1)
{
    int blk = blockIdx.x;
    if (blk < 512)       split_role(blk,        W1, 512, 256, 512,  w1);
    else if (blk < 576)  split_role(blk - 512,  W2, 256, 64,  256,  w2);
    else if (blk < 1408) split_role(blk - 576,  T0, 415, 512, YSTR, t0);
    else                 split_role(blk - 1408, T1, 512, 256, 512,  t1);
}

// ======= embedding gather + pool: 2 tasks per warp, interleaved (MLP 8) ========
__global__ __launch_bounds__(256)
void k_gather(const void* __restrict__ idx_raw,
              const float* __restrict__ tables, float* __restrict__ feats)
{
    const int gwarp = (blockIdx.x * blockDim.x + threadIdx.x) >> 5;
    const int lane = threadIdx.x & 31;
    const long long t0 = (long long)gwarp * 2;

    const long long* p64 = (const long long*)idx_raw;
    long long v0 = p64[0], v1 = p64[123], v2 = p64[4567], v3 = p64[89012];
    const bool is64 = (v0 >= 0 && v0 < Nrows) && (v1 >= 0 && v1 < Nrows) &&
                      (v2 >= 0 && v2 < Nrows) && (v3 >= 0 && v3 < Nrows);
    const int* p32 = (const int*)idx_raw;

    int f[2], b[2];
    long long rows[2][Lk];
    #pragma unroll
    for (int u = 0; u < 2; u++) {
        long long t = t0 + u;
        f[u] = (int)(t / Bsz); b[u] = (int)(t % Bsz);
        long long base = (long long)f[u] * Bsz * Lk + (long long)b[u] * Lk;
        #pragma unroll
        for (int l = 0; l < Lk; l++)
            rows[u][l] = is64 ? p64[base + l] : (long long)p32[base + l];
    }

    // issue all 8 row loads before accumulating (MLP 8)
    float2 v[2][Lk];
    #pragma unroll
    for (int u = 0; u < 2; u++)
        #pragma unroll
        for (int l = 0; l < Lk; l++)
            v[u][l] = *(const float2*)(tables +
                ((long long)f[u] * Nrows + rows[u][l]) * Dim + lane * 2);

    #pragma unroll
    for (int u = 0; u < 2; u++) {
        float2 acc = make_float2(0.f, 0.f);
        #pragma unroll
        for (int l = 0; l < Lk; l++) { acc.x += v[u][l].x; acc.y += v[u][l].y; }
        *(float2*)(feats + (size_t)b[u] * (NFEAT * Dim) +
                   (f[u] + 1) * Dim + lane * 2) = acc;
    }
}

// ======= tensor-core interaction: 1 warp/sample, asymmetric 2-term gram ========
__global__ __launch_bounds__(128)
void interact_mma(const float* __restrict__ feats, __half* __restrict__ y)
{
    __shared__ __half sF[4][2][32 * ILD];
    const int warp = threadIdx.x >> 5, lane = threadIdx.x & 31;
    const int b = blockIdx.x * 4 + warp;
    const int gid = lane >> 2, tig = lane & 3;
    __half* Fh = &sF[warp][0][0];
    __half* Fl = &sF[warp][1][0];
    const float* fr = feats + (size_t)b * (NFEAT * Dim);

    #pragma unroll
    for (int s = 0; s < 32; s++) {
        int idx = lane + s * 32;
        int r = idx >> 5, cp = (idx & 31) * 2;
        float2 v = (r < NFEAT) ? *(const float2*)(fr + r * 64 + cp)
                               : make_float2(0.f, 0.f);
        __half2 h = __floats2half2_rn(v.x, v.y);
        float2 hd = __half22float2(h);
        __half2 l = __floats2half2_rn(v.x - hd.x, v.y - hd.y);
        *(__half2*)&Fh[r * ILD + cp] = h;
        *(__half2*)&Fl[r * ILD + cp] = l;
    }
    __syncwarp();

    float acc[2][4][4] = {};
    #pragma unroll
    for (int ks = 0; ks < 64; ks += 16) {
        uint32_t ah[2][4], bh[4][2], bl[4][2];
        #pragma unroll
        for (int mt = 0; mt < 2; mt++) {
            int r0 = (mt * 16 + gid) * ILD + ks + 2 * tig;
            ah[mt][0] = *(const uint32_t*)&Fh[r0];
            ah[mt][1] = *(const uint32_t*)&Fh[r0 + 8 * ILD];
            ah[mt][2] = *(const uint32_t*)&Fh[r0 + 8];
            ah[mt][3] = *(const uint32_t*)&Fh[r0 + 8 * ILD + 8];
        }
        #pragma unroll
        for (int nt = 0; nt < 4; nt++) {
            int n0 = (nt * 8 + gid) * ILD + ks + 2 * tig;
            bh[nt][0] = *(const uint32_t*)&Fh[n0];
            bh[nt][1] = *(const uint32_t*)&Fh[n0 + 8];
            bl[nt][0] = *(const uint32_t*)&Fl[n0];
            bl[nt][1] = *(const uint32_t*)&Fl[n0 + 8];
        }
        #pragma unroll
        for (int mt = 0; mt < 2; mt++)
            #pragma unroll
            for (int nt = 0; nt < 4; nt++) {
                MMA_F16(acc[mt][nt], ah[mt], bh[nt][0], bh[nt][1]);
                MMA_F16(acc[mt][nt], ah[mt], bl[nt][0], bl[nt][1]);
            }
    }

    __half* yr = y + (size_t)b * YSTR;
    #pragma unroll
    for (int s = 0; s < 2; s++) yr[lane + s * 32] = Fh[lane + s * 32];
    if (lane == 0) yr[OVERIN] = __float2half_rn(0.f);

    #pragma unroll
    for (int mt = 0; mt < 2; mt++)
        #pragma unroll
        for (int nt = 0; nt < 4; nt++)
            #pragma unroll
            for (int e = 0; e < 4; e++) {
                int m = mt * 16 + gid + (e >> 1) * 8;
                int n = nt * 8 + tig * 2 + (e & 1);
                if (n > m && n < NFEAT) {
                    int p = m * (2 * NFEAT - m - 1) / 2 + (n - m - 1);
                    yr[Dim + p] = __float2half_rn(acc[mt][nt][e]);
                }
            }
}

// ======= final layer ============================================================
__global__ __launch_bounds__(256)
void gemv_final(const __half* __restrict__ X, const float* __restrict__ w,
                const float* __restrict__ bias, float* __restrict__ out)
{
    const int row = (blockIdx.x * blockDim.x + threadIdx.x) >> 5;
    const int lane = threadIdx.x & 31;
    if (row >= Bsz) return;
    uint4 hv = *(const uint4*)(X + (size_t)row * 256 + lane * 8);
    const __half2* hp = (const __half2*)&hv;
    float s = 0.f;
    #pragma unroll
    for (int q = 0; q < 4; q++) {
        float2 h2 = __half22float2(hp[q]);
        s = fmaf(h2.x, w[lane * 8 + q * 2], s);
        s = fmaf(h2.y, w[lane * 8 + q * 2 + 1], s);
    }
    #pragma unroll
    for (int o = 16; o; o >>= 1) s += __shfl_down_sync(0xffffffffu, s, o);
    if (lane == 0) out[row] = s + bias[0];
}

// -----------------------------------------------------------------------------
static void* sym_addr(const void* sym)
{
    void* p = nullptr;
    cudaGetSymbolAddress(&p, sym);
    return p;
}

extern "C" void kernel_launch(void* const* d_in, const int* in_sizes, int n_in,
                              void* d_out, int out_size)
{
    (void)in_sizes; (void)n_in; (void)out_size;

    const float* dense  = (const float*)d_in[0];
    const void*  sp_idx = d_in[1];
    const float* tables = (const float*)d_in[2];
    const float* botW0 = (const float*)d_in[3],  *botb0 = (const float*)d_in[4];
    const float* botW1 = (const float*)d_in[5],  *botb1 = (const float*)d_in[6];
    const float* botW2 = (const float*)d_in[7],  *botb2 = (const float*)d_in[8];
    const float* topW0 = (const float*)d_in[9],  *topb0 = (const float*)d_in[10];
    const float* topW1 = (const float*)d_in[11], *topb1 = (const float*)d_in[12];
    const float* topW2 = (const float*)d_in[13], *topb2 = (const float*)d_in[14];
    float* out = (float*)d_out;

    float*  feats = (float*)sym_addr(g_feats);
    __half* h1 = (__half*)sym_addr(g_h1);
    __half* h2 = (__half*)sym_addr(g_h2);
    __half* y  = (__half*)sym_addr(g_y);
    __half* w1 = (__half*)sym_addr(g_w1);
    __half* w2 = (__half*)sym_addr(g_w2);
    __half* t0 = (__half*)sym_addr(g_t0);
    __half* t1 = (__half*)sym_addr(g_t1);

    // #1 splits, #2 b0, #3 gather, #4 b1 (profiled), #5 b2, #6 interact,
    // #7 t0, #8 t1, #9 gemv
    k_split<<<1920, 256>>>(botW1, w1, botW2, w2, topW0, t0, topW1, t1);
    k_b0<<<dim3(8, 128), 256>>>(dense, botW0, botb0, h1);
    k_gather<<<(Fn * Bsz / 2 * 32) / 256, 256>>>(sp_idx, tables, feats);
    k_gemm<<<dim3(4, 128), 256>>>(h1, w1, botb1, 512, h2, 256);
    k_b2<<<256, 128>>>(h2, w2, botb2, feats);
    interact_mma<<<Bsz / 4, 128>>>(feats, y);
    k_gemm<<<dim3(8, 128), 256>>>(y, t0, topb0, YSTR, h1, 512);
    k_gemm<<<dim3(4, 128), 256>>>(h1, t1, topb1, 512, h2, 256);
    gemv_final<<<(Bsz * 32) / 256, 256>>>(h2, topW2, topb2, out);
}

// round 16
// speedup vs baseline: 1.6313x; 1.0758x over previous
#include <cuda_runtime.h>
#include <cuda_fp16.h>
#include <cstdint>

#define Bsz 16384
#define Fn 26
#define Nrows 100000
#define Dim 64
#define Lk 4
#define NFEAT 27
#define NPAIRS 351
#define OVERIN 415
#define YSTR 416
#define LDA 40
#define ILD 72
#define FSTR (NFEAT * Dim)    // 1728

// ---------------- scratch -----------------------------------------------------
__device__ __half g_feats[(size_t)Bsz * FSTR];     // fp16 single plane
__device__ __half g_h1[(size_t)Bsz * 512];
__device__ __half g_h2[(size_t)Bsz * 256];
__device__ __half g_y[(size_t)Bsz * YSTR];
__device__ __half g_w1[256 * 512];
__device__ __half g_w2[64 * 256];
__device__ __half g_t0[512 * YSTR];
__device__ __half g_t1[256 * 512];

#define MMA_F16(c, a, b0v, b1v) \
    asm volatile("mma.sync.aligned.m16n8k16.row.col.f32.f16.f16.f32 " \
        "{%0,%1,%2,%3}, {%4,%5,%6,%7}, {%8,%9}, {%0,%1,%2,%3};" \
        : "+f"((c)[0]), "+f"((c)[1]), "+f"((c)[2]), "+f"((c)[3]) \
        : "r"((a)[0]), "r"((a)[1]), "r"((a)[2]), "r"((a)[3]), "r"(b0v), "r"(b1v))

#define CP16(dst, src) \
    asm volatile("cp.async.cg.shared.global [%0], [%1], 16;" \
        :: "r"(dst), "l"(src))
#define CP_COMMIT() asm volatile("cp.async.commit_group;" ::: "memory")
#define CP_WAIT1()  asm volatile("cp.async.wait_group 1;" ::: "memory")
#define CP_WAIT0()  asm volatile("cp.async.wait_group 0;" ::: "memory")

__device__ __forceinline__ uint32_t smem_u32(const void* p) {
    uint32_t a;
    asm("{ .reg .u64 t; cvta.to.shared.u64 t, %1; cvt.u32.u64 %0, t; }"
        : "=r"(a) : "l"(p));
    return a;
}

// ---- 32-K mma chunk: As rows x LDA, Bs[64][LDA], scalar frag loads -----------
__device__ __forceinline__ void mma_chunk(const __half* As, const __half* Bs,
    int wm, int wn, int gid, int tig, float acc[2][4][4])
{
    #pragma unroll
    for (int ks = 0; ks < 32; ks += 16) {
        uint32_t a[2][4], bh[4][2];
        #pragma unroll
        for (int mt = 0; mt < 2; mt++) {
            int r0 = (wm * 32 + mt * 16 + gid) * LDA + ks + 2 * tig;
            a[mt][0] = *(const uint32_t*)&As[r0];
            a[mt][1] = *(const uint32_t*)&As[r0 + 8 * LDA];
            a[mt][2] = *(const uint32_t*)&As[r0 + 8];
            a[mt][3] = *(const uint32_t*)&As[r0 + 8 * LDA + 8];
        }
        #pragma unroll
        for (int nt = 0; nt < 4; nt++) {
            int n0 = (wn * 32 + nt * 8 + gid) * LDA + ks + 2 * tig;
            bh[nt][0] = *(const uint32_t*)&Bs[n0];
            bh[nt][1] = *(const uint32_t*)&Bs[n0 + 8];
        }
        #pragma unroll
        for (int mt = 0; mt < 2; mt++)
            #pragma unroll
            for (int nt = 0; nt < 4; nt++)
                MMA_F16(acc[mt][nt], a[mt], bh[nt][0], bh[nt][1]);
    }
}

__device__ __forceinline__ void gemm_epi(float acc[2][4][4],
    const float* __restrict__ bias, int bm, int bn, int wm, int wn,
    int gid, int tig, int relu, __half* __restrict__ Ch, int ldch)
{
    #pragma unroll
    for (int mt = 0; mt < 2; mt++) {
        int r0 = bm + wm * 32 + mt * 16 + gid;
        #pragma unroll
        for (int nt = 0; nt < 4; nt++) {
            int cc = bn + wn * 32 + nt * 8 + tig * 2;
            float b0 = bias[cc], b1 = bias[cc + 1];
            float v00 = acc[mt][nt][0] + b0, v01 = acc[mt][nt][1] + b1;
            float v10 = acc[mt][nt][2] + b0, v11 = acc[mt][nt][3] + b1;
            if (relu) {
                v00 = fmaxf(v00, 0.f); v01 = fmaxf(v01, 0.f);
                v10 = fmaxf(v10, 0.f); v11 = fmaxf(v11, 0.f);
            }
            *(__half2*)&Ch[(size_t)r0 * ldch + cc]       = __floats2half2_rn(v00, v01);
            *(__half2*)&Ch[(size_t)(r0 + 8) * ldch + cc] = __floats2half2_rn(v10, v11);
        }
    }
}

// ======= main GEMM: CTA 128x64, 3-stage cp.async pipeline, 1 sync / K-iter ====
__global__ __launch_bounds__(256)
void k_gemm(const __half* __restrict__ A, const __half* __restrict__ B,
            const float* __restrict__ bias, int K, __half* __restrict__ Ch,
            int ldch)
{
    __shared__ __align__(16) __half sm[3 * 7680];

    const int tid = threadIdx.x, warp = tid >> 5, lane = tid & 31;
    const int wm = warp & 3, wn = warp >> 2;
    const int gid = lane >> 2, tig = lane & 3;
    const int bm = blockIdx.y * 128, bn = blockIdx.x * 64;
    const uint32_t sb = smem_u32(sm);

    float acc[2][4][4] = {};
    const int kIter = K >> 5;

    const int rA = tid >> 2, kqA = tid & 3;
    auto issue = [&](int it) {
        const int k0 = it * 32;
        const uint32_t base = sb + (uint32_t)((it % 3) * 15360);
        CP16(base + rA * 80 + kqA * 16,
             A + (size_t)(bm + rA) * K + k0 + kqA * 8);
        CP16(base + (rA + 64) * 80 + kqA * 16,
             A + (size_t)(bm + rA + 64) * K + k0 + kqA * 8);
        CP16(base + 10240 + rA * 80 + kqA * 16,
             B + (size_t)(bn + rA) * K + k0 + kqA * 8);
        CP_COMMIT();
    };

    issue(0);
    if (kIter > 1) issue(1);
    for (int it = 0; it < kIter; it++) {
        if (it + 2 <= kIter) { CP_WAIT1(); } else { CP_WAIT0(); }
        __syncthreads();
        if (it + 2 < kIter) issue(it + 2);
        __half* As = sm + (it % 3) * 7680;
        __half* Bs = As + 5120;
        mma_chunk(As, Bs, wm, wn, gid, tig, acc);
    }
    gemm_epi(acc, bias, bm, bn, wm, wn, gid, tig, 1, Ch, ldch);
}

// ======= b2: CTA 64x64 (128 thr, warps 2x2), K=256, fp16 out into feats =======
__global__ __launch_bounds__(128)
void k_b2(const __half* __restrict__ A, const __half* __restrict__ B,
          const float* __restrict__ bias, __half* __restrict__ Cf)
{
    __shared__ __align__(16) __half sm[2][5120];

    const int tid = threadIdx.x, warp = tid >> 5, lane = tid & 31;
    const int wm = warp & 1, wn = warp >> 1;
    const int gid = lane >> 2, tig = lane & 3;
    const int bm = blockIdx.x * 64, bn = 0;
    const int K = 256;

    float acc[2][4][4] = {};
    uint4 pa[2], pb[2];

    auto prefetch = [&](int it) {
        const int k0 = it * 32;
        #pragma unroll
        for (int s = 0; s < 2; s++) {
            int idx = tid + s * 128;
            int r = idx >> 2, kq = idx & 3;
            pa[s] = *(const uint4*)(A + (size_t)(bm + r) * K + k0 + kq * 8);
            pb[s] = *(const uint4*)(B + (size_t)r * K + k0 + kq * 8);
        }
    };

    prefetch(0);
    for (int it = 0; it < 8; it++) {
        __half* As = sm[it & 1];
        __half* Bs = sm[it & 1] + 2560;
        #pragma unroll
        for (int s = 0; s < 2; s++) {
            int idx = tid + s * 128;
            int r = idx >> 2, kq = idx & 3;
            *(uint4*)&As[r * LDA + kq * 8] = pa[s];
            *(uint4*)&Bs[r * LDA + kq * 8] = pb[s];
        }
        __syncthreads();
        if (it + 1 < 8) prefetch(it + 1);
        mma_chunk(As, Bs, wm, wn, gid, tig, acc);
    }
    gemm_epi(acc, bias, bm, bn, wm, wn, gid, tig, 1, Cf, FSTR);
}

// ======= b0: K=32 (13 real), fp32 inputs converted inline ======================
__global__ __launch_bounds__(256)
void k_b0(const float* __restrict__ dense, const float* __restrict__ W0,
          const float* __restrict__ bias, __half* __restrict__ h1)
{
    __shared__ __align__(16) __half sm[7680];
    __half* As = sm;
    __half* Bs = sm + 5120;
    const int tid = threadIdx.x, warp = tid >> 5, lane = tid & 31;
    const int wm = warp & 3, wn = warp >> 2;
    const int gid = lane >> 2, tig = lane & 3;
    const int bm = blockIdx.y * 128, bn = blockIdx.x * 64;

    #pragma unroll
    for (int s = 0; s < 8; s++) {
        int idx = tid + s * 256;
        int r = idx >> 4, cp = (idx & 15) * 2;
        float x0 = (cp < 13)     ? dense[(size_t)(bm + r) * 13 + cp]     : 0.f;
        float x1 = (cp + 1 < 13) ? dense[(size_t)(bm + r) * 13 + cp + 1] : 0.f;
        *(__half2*)&As[r * LDA + cp] = __floats2half2_rn(x0, x1);
    }
    #pragma unroll
    for (int s = 0; s < 8; s++) {
        int idx = tid + s * 256;
        int n = idx & 63, k = idx >> 6;
        float v = (k < 13) ? W0[(size_t)k * 512 + bn + n] : 0.f;
        Bs[n * LDA + k] = __float2half_rn(v);
    }
    __syncthreads();

    float acc[2][4][4] = {};
    mma_chunk(As, Bs, wm, wn, gid, tig, acc);
    gemm_epi(acc, bias, bm, bn, wm, wn, gid, tig, 1, h1, 512);
}

// ======= all weight splits in one launch ========================================
__device__ void split_role(int local, const float* __restrict__ W, int K, int N,
                           int Kpad, __half* __restrict__ o)
{
    int idx = local * 256 + threadIdx.x;
    if (idx >= N * Kpad) return;
    int n = idx / Kpad, k = idx - n * Kpad;
    float v = (k < K) ? W[(size_t)k * N + n] : 0.f;
    o[idx] = __float2half_rn(v);
}

__global__ __launch_bounds__(256)
void k_split(const float* W1, __half* w1, const float* W2, __half* w2,
             const float* T0, __half* t0, const float* T1, __half* t1)
{
    int blk = blockIdx.x;
    if (blk < 512)       split_role(blk,        W1, 512, 256, 512,  w1);
    else if (blk < 576)  split_role(blk - 512,  W2, 256, 64,  256,  w2);
    else if (blk < 1408) split_role(blk - 576,  T0, 415, 512, YSTR, t0);
    else                 split_role(blk - 1408, T1, 512, 256, 512,  t1);
}

// ======= embedding gather + pool: 2 tasks per warp (MLP 8), fp16 output ========
__global__ __launch_bounds__(256)
void k_gather(const void* __restrict__ idx_raw,
              const float* __restrict__ tables, __half* __restrict__ feats)
{
    const int gwarp = (blockIdx.x * blockDim.x + threadIdx.x) >> 5;
    const int lane = threadIdx.x & 31;
    const long long t0 = (long long)gwarp * 2;

    const long long* p64 = (const long long*)idx_raw;
    long long v0 = p64[0], v1 = p64[123], v2 = p64[4567], v3 = p64[89012];
    const bool is64 = (v0 >= 0 && v0 < Nrows) && (v1 >= 0 && v1 < Nrows) &&
                      (v2 >= 0 && v2 < Nrows) && (v3 >= 0 && v3 < Nrows);
    const int* p32 = (const int*)idx_raw;

    int f[2], b[2];
    long long rows[2][Lk];
    #pragma unroll
    for (int u = 0; u < 2; u++) {
        long long t = t0 + u;
        f[u] = (int)(t / Bsz); b[u] = (int)(t % Bsz);
        long long base = (long long)f[u] * Bsz * Lk + (long long)b[u] * Lk;
        #pragma unroll
        for (int l = 0; l < Lk; l++)
            rows[u][l] = is64 ? p64[base + l] : (long long)p32[base + l];
    }

    float2 v[2][Lk];
    #pragma unroll
    for (int u = 0; u < 2; u++)
        #pragma unroll
        for (int l = 0; l < Lk; l++)
            v[u][l] = *(const float2*)(tables +
                ((long long)f[u] * Nrows + rows[u][l]) * Dim + lane * 2);

    #pragma unroll
    for (int u = 0; u < 2; u++) {
        float2 acc = make_float2(0.f, 0.f);
        #pragma unroll
        for (int l = 0; l < Lk; l++) { acc.x += v[u][l].x; acc.y += v[u][l].y; }
        *(__half2*)(feats + (size_t)b[u] * FSTR + (f[u] + 1) * Dim + lane * 2) =
            __floats2half2_rn(acc.x, acc.y);
    }
}

// ======= interaction: 1 warp/sample, 1-term fp16 gram ==========================
__global__ __launch_bounds__(128)
void interact_mma(const __half* __restrict__ feats, __half* __restrict__ y)
{
    __shared__ __half sF[4][32 * ILD];
    const int warp = threadIdx.x >> 5, lane = threadIdx.x & 31;
    const int b = blockIdx.x * 4 + warp;
    const int gid = lane >> 2, tig = lane & 3;
    __half* Fh = &sF[warp][0];
    const __half* fr = feats + (size_t)b * FSTR;

    // load 32x64 fp16 (rows >= NFEAT zeroed): 256 uint4, 8 per lane
    #pragma unroll
    for (int s = 0; s < 8; s++) {
        int idx = lane + s * 32;
        int r = idx >> 3, q = idx & 7;
        uint4 vv = make_uint4(0u, 0u, 0u, 0u);
        if (r < NFEAT) vv = *(const uint4*)(fr + r * 64 + q * 8);
        *(uint4*)&Fh[r * ILD + q * 8] = vv;
    }
    __syncwarp();

    float acc[2][4][4] = {};
    #pragma unroll
    for (int ks = 0; ks < 64; ks += 16) {
        uint32_t ah[2][4], bh[4][2];
        #pragma unroll
        for (int mt = 0; mt < 2; mt++) {
            int r0 = (mt * 16 + gid) * ILD + ks + 2 * tig;
            ah[mt][0] = *(const uint32_t*)&Fh[r0];
            ah[mt][1] = *(const uint32_t*)&Fh[r0 + 8 * ILD];
            ah[mt][2] = *(const uint32_t*)&Fh[r0 + 8];
            ah[mt][3] = *(const uint32_t*)&Fh[r0 + 8 * ILD + 8];
        }
        #pragma unroll
        for (int nt = 0; nt < 4; nt++) {
            int n0 = (nt * 8 + gid) * ILD + ks + 2 * tig;
            bh[nt][0] = *(const uint32_t*)&Fh[n0];
            bh[nt][1] = *(const uint32_t*)&Fh[n0 + 8];
        }
        #pragma unroll
        for (int mt = 0; mt < 2; mt++)
            #pragma unroll
            for (int nt = 0; nt < 4; nt++)
                MMA_F16(acc[mt][nt], ah[mt], bh[nt][0], bh[nt][1]);
    }

    __half* yr = y + (size_t)b * YSTR;
    #pragma unroll
    for (int s = 0; s < 2; s++) yr[lane + s * 32] = Fh[lane + s * 32];
    if (lane == 0) yr[OVERIN] = __float2half_rn(0.f);

    #pragma unroll
    for (int mt = 0; mt < 2; mt++)
        #pragma unroll
        for (int nt = 0; nt < 4; nt++)
            #pragma unroll
            for (int e = 0; e < 4; e++) {
                int m = mt * 16 + gid + (e >> 1) * 8;
                int n = nt * 8 + tig * 2 + (e & 1);
                if (n > m && n < NFEAT) {
                    int p = m * (2 * NFEAT - m - 1) / 2 + (n - m - 1);
                    yr[Dim + p] = __float2half_rn(acc[mt][nt][e]);
                }
            }
}

// ======= final layer ============================================================
__global__ __launch_bounds__(256)
void gemv_final(const __half* __restrict__ X, const float* __restrict__ w,
                const float* __restrict__ bias, float* __restrict__ out)
{
    const int row = (blockIdx.x * blockDim.x + threadIdx.x) >> 5;
    const int lane = threadIdx.x & 31;
    if (row >= Bsz) return;
    uint4 hv = *(const uint4*)(X + (size_t)row * 256 + lane * 8);
    const __half2* hp = (const __half2*)&hv;
    float s = 0.f;
    #pragma unroll
    for (int q = 0; q < 4; q++) {
        float2 h2 = __half22float2(hp[q]);
        s = fmaf(h2.x, w[lane * 8 + q * 2], s);
        s = fmaf(h2.y, w[lane * 8 + q * 2 + 1], s);
    }
    #pragma unroll
    for (int o = 16; o; o >>= 1) s += __shfl_down_sync(0xffffffffu, s, o);
    if (lane == 0) out[row] = s + bias[0];
}

// -----------------------------------------------------------------------------
static void* sym_addr(const void* sym)
{
    void* p = nullptr;
    cudaGetSymbolAddress(&p, sym);
    return p;
}

extern "C" void kernel_launch(void* const* d_in, const int* in_sizes, int n_in,
                              void* d_out, int out_size)
{
    (void)in_sizes; (void)n_in; (void)out_size;

    const float* dense  = (const float*)d_in[0];
    const void*  sp_idx = d_in[1];
    const float* tables = (const float*)d_in[2];
    const float* botW0 = (const float*)d_in[3],  *botb0 = (const float*)d_in[4];
    const float* botW1 = (const float*)d_in[5],  *botb1 = (const float*)d_in[6];
    const float* botW2 = (const float*)d_in[7],  *botb2 = (const float*)d_in[8];
    const float* topW0 = (const float*)d_in[9],  *topb0 = (const float*)d_in[10];
    const float* topW1 = (const float*)d_in[11], *topb1 = (const float*)d_in[12];
    const float* topW2 = (const float*)d_in[13], *topb2 = (const float*)d_in[14];
    float* out = (float*)d_out;

    __half* feats = (__half*)sym_addr(g_feats);
    __half* h1 = (__half*)sym_addr(g_h1);
    __half* h2 = (__half*)sym_addr(g_h2);
    __half* y  = (__half*)sym_addr(g_y);
    __half* w1 = (__half*)sym_addr(g_w1);
    __half* w2 = (__half*)sym_addr(g_w2);
    __half* t0 = (__half*)sym_addr(g_t0);
    __half* t1 = (__half*)sym_addr(g_t1);

    // #1 splits, #2 b0, #3 gather, #4 b1 (profiled), #5 b2, #6 interact,
    // #7 t0, #8 t1, #9 gemv
    k_split<<<1920, 256>>>(botW1, w1, botW2, w2, topW0, t0, topW1, t1);
    k_b0<<<dim3(8, 128), 256>>>(dense, botW0, botb0, h1);
    k_gather<<<(Fn * Bsz / 2 * 32) / 256, 256>>>(sp_idx, tables, feats);
    k_gemm<<<dim3(4, 128), 256>>>(h1, w1, botb1, 512, h2, 256);
    k_b2<<<256, 128>>>(h2, w2, botb2, feats);
    interact_mma<<<Bsz / 4, 128>>>(feats, y);
    k_gemm<<<dim3(8, 128), 256>>>(y, t0, topb0, YSTR, h1, 512);
    k_gemm<<<dim3(4, 128), 256>>>(h1, t1, topb1, 512, h2, 256);
    gemv_final<<<(Bsz * 32) / 256, 256>>>(h2, topW2, topb2, out);
}

// round 17
// speedup vs baseline: 1.6605x; 1.0179x over previous
#include <cuda_runtime.h>
#include <cuda_fp16.h>
#include <cstdint>

#define Bsz 16384
#define Fn 26
#define Nrows 100000
#define Dim 64
#define Lk 4
#define NFEAT 27
#define NPAIRS 351
#define OVERIN 415
#define YSTR 416
#define LDA 40
#define ILD 72
#define FSTR (NFEAT * Dim)    // 1728

#define GSTAGE 20480          // bytes per pipeline stage (A 10240 + B 10240)
#define GSMEM  (3 * GSTAGE)   // 61440 B dynamic smem

// ---------------- scratch -----------------------------------------------------
__device__ __half g_feats[(size_t)Bsz * FSTR];
__device__ __half g_h1[(size_t)Bsz * 512];
__device__ __half g_h2[(size_t)Bsz * 256];
__device__ __half g_y[(size_t)Bsz * YSTR];
__device__ __half g_w1[256 * 512];
__device__ __half g_w2[64 * 256];
__device__ __half g_t0[512 * YSTR];
__device__ __half g_t1[256 * 512];

#define MMA_F16(c, a, b0v, b1v) \
    asm volatile("mma.sync.aligned.m16n8k16.row.col.f32.f16.f16.f32 " \
        "{%0,%1,%2,%3}, {%4,%5,%6,%7}, {%8,%9}, {%0,%1,%2,%3};" \
        : "+f"((c)[0]), "+f"((c)[1]), "+f"((c)[2]), "+f"((c)[3]) \
        : "r"((a)[0]), "r"((a)[1]), "r"((a)[2]), "r"((a)[3]), "r"(b0v), "r"(b1v))

#define CP16(dst, src) \
    asm volatile("cp.async.cg.shared.global [%0], [%1], 16;" \
        :: "r"(dst), "l"(src))
#define CP_COMMIT() asm volatile("cp.async.commit_group;" ::: "memory")
#define CP_WAIT1()  asm volatile("cp.async.wait_group 1;" ::: "memory")
#define CP_WAIT0()  asm volatile("cp.async.wait_group 0;" ::: "memory")

__device__ __forceinline__ uint32_t smem_u32(const void* p) {
    uint32_t a;
    asm("{ .reg .u64 t; cvta.to.shared.u64 t, %1; cvt.u32.u64 %0, t; }"
        : "=r"(a) : "l"(p));
    return a;
}

// ---- 32-K mma chunk, warp tile 32x32 (b0/b2 path) -----------------------------
__device__ __forceinline__ void mma_chunk(const __half* As, const __half* Bs,
    int wm, int wn, int gid, int tig, float acc[2][4][4])
{
    #pragma unroll
    for (int ks = 0; ks < 32; ks += 16) {
        uint32_t a[2][4], bh[4][2];
        #pragma unroll
        for (int mt = 0; mt < 2; mt++) {
            int r0 = (wm * 32 + mt * 16 + gid) * LDA + ks + 2 * tig;
            a[mt][0] = *(const uint32_t*)&As[r0];
            a[mt][1] = *(const uint32_t*)&As[r0 + 8 * LDA];
            a[mt][2] = *(const uint32_t*)&As[r0 + 8];
            a[mt][3] = *(const uint32_t*)&As[r0 + 8 * LDA + 8];
        }
        #pragma unroll
        for (int nt = 0; nt < 4; nt++) {
            int n0 = (wn * 32 + nt * 8 + gid) * LDA + ks + 2 * tig;
            bh[nt][0] = *(const uint32_t*)&Bs[n0];
            bh[nt][1] = *(const uint32_t*)&Bs[n0 + 8];
        }
        #pragma unroll
        for (int mt = 0; mt < 2; mt++)
            #pragma unroll
            for (int nt = 0; nt < 4; nt++)
                MMA_F16(acc[mt][nt], a[mt], bh[nt][0], bh[nt][1]);
    }
}

// ---- 32-K mma chunk, warp tile 32x64 (main GEMM, CTA 128x128) ------------------
__device__ __forceinline__ void mma_chunk128(const __half* As, const __half* Bs,
    int wm, int wn, int gid, int tig, float acc[2][8][4])
{
    #pragma unroll
    for (int ks = 0; ks < 32; ks += 16) {
        uint32_t a[2][4], bh[8][2];
        #pragma unroll
        for (int mt = 0; mt < 2; mt++) {
            int r0 = (wm * 32 + mt * 16 + gid) * LDA + ks + 2 * tig;
            a[mt][0] = *(const uint32_t*)&As[r0];
            a[mt][1] = *(const uint32_t*)&As[r0 + 8 * LDA];
            a[mt][2] = *(const uint32_t*)&As[r0 + 8];
            a[mt][3] = *(const uint32_t*)&As[r0 + 8 * LDA + 8];
        }
        #pragma unroll
        for (int nt = 0; nt < 8; nt++) {
            int n0 = (wn * 64 + nt * 8 + gid) * LDA + ks + 2 * tig;
            bh[nt][0] = *(const uint32_t*)&Bs[n0];
            bh[nt][1] = *(const uint32_t*)&Bs[n0 + 8];
        }
        #pragma unroll
        for (int mt = 0; mt < 2; mt++)
            #pragma unroll
            for (int nt = 0; nt < 8; nt++)
                MMA_F16(acc[mt][nt], a[mt], bh[nt][0], bh[nt][1]);
    }
}

__device__ __forceinline__ void gemm_epi(float acc[2][4][4],
    const float* __restrict__ bias, int bm, int bn, int wm, int wn,
    int gid, int tig, int relu, __half* __restrict__ Ch, int ldch)
{
    #pragma unroll
    for (int mt = 0; mt < 2; mt++) {
        int r0 = bm + wm * 32 + mt * 16 + gid;
        #pragma unroll
        for (int nt = 0; nt < 4; nt++) {
            int cc = bn + wn * 32 + nt * 8 + tig * 2;
            float b0 = bias[cc], b1 = bias[cc + 1];
            float v00 = acc[mt][nt][0] + b0, v01 = acc[mt][nt][1] + b1;
            float v10 = acc[mt][nt][2] + b0, v11 = acc[mt][nt][3] + b1;
            if (relu) {
                v00 = fmaxf(v00, 0.f); v01 = fmaxf(v01, 0.f);
                v10 = fmaxf(v10, 0.f); v11 = fmaxf(v11, 0.f);
            }
            *(__half2*)&Ch[(size_t)r0 * ldch + cc]       = __floats2half2_rn(v00, v01);
            *(__half2*)&Ch[(size_t)(r0 + 8) * ldch + cc] = __floats2half2_rn(v10, v11);
        }
    }
}

// ======= main GEMM: CTA 128x128, 3-stage cp.async, 1 sync / K-iter ============
__global__ __launch_bounds__(256)
void k_gemm(const __half* __restrict__ A, const __half* __restrict__ B,
            const float* __restrict__ bias, int K, __half* __restrict__ Ch,
            int ldch)
{
    extern __shared__ __align__(16) __half sm[];

    const int tid = threadIdx.x, warp = tid >> 5, lane = tid & 31;
    const int wm = warp & 3, wn = warp >> 2;           // 4M x 2N
    const int gid = lane >> 2, tig = lane & 3;
    const int bm = blockIdx.y * 128, bn = blockIdx.x * 128;
    const uint32_t sb = smem_u32(sm);

    float acc[2][8][4] = {};
    const int kIter = K >> 5;

    const int rA = tid >> 2, kqA = tid & 3;            // rows 0..63; +64 pass
    auto issue = [&](int it) {
        const int k0 = it * 32;
        const uint32_t base = sb + (uint32_t)((it % 3) * GSTAGE);
        CP16(base + rA * 80 + kqA * 16,
             A + (size_t)(bm + rA) * K + k0 + kqA * 8);
        CP16(base + (rA + 64) * 80 + kqA * 16,
             A + (size_t)(bm + rA + 64) * K + k0 + kqA * 8);
        CP16(base + 10240 + rA * 80 + kqA * 16,
             B + (size_t)(bn + rA) * K + k0 + kqA * 8);
        CP16(base + 10240 + (rA + 64) * 80 + kqA * 16,
             B + (size_t)(bn + rA + 64) * K + k0 + kqA * 8);
        CP_COMMIT();
    };

    issue(0);
    if (kIter > 1) issue(1);
    for (int it = 0; it < kIter; it++) {
        if (it + 2 <= kIter) { CP_WAIT1(); } else { CP_WAIT0(); }
        __syncthreads();
        if (it + 2 < kIter) issue(it + 2);
        __half* As = sm + (it % 3) * (GSTAGE / 2);
        __half* Bs = As + 5120;
        mma_chunk128(As, Bs, wm, wn, gid, tig, acc);
    }

    #pragma unroll
    for (int mt = 0; mt < 2; mt++) {
        int r0 = bm + wm * 32 + mt * 16 + gid;
        #pragma unroll
        for (int nt = 0; nt < 8; nt++) {
            int cc = bn + wn * 64 + nt * 8 + tig * 2;
            float b0 = bias[cc], b1 = bias[cc + 1];
            float v00 = fmaxf(acc[mt][nt][0] + b0, 0.f);
            float v01 = fmaxf(acc[mt][nt][1] + b1, 0.f);
            float v10 = fmaxf(acc[mt][nt][2] + b0, 0.f);
            float v11 = fmaxf(acc[mt][nt][3] + b1, 0.f);
            *(__half2*)&Ch[(size_t)r0 * ldch + cc]       = __floats2half2_rn(v00, v01);
            *(__half2*)&Ch[(size_t)(r0 + 8) * ldch + cc] = __floats2half2_rn(v10, v11);
        }
    }
}

// ======= b2: CTA 64x64 (128 thr, warps 2x2), K=256, fp16 out into feats =======
__global__ __launch_bounds__(128)
void k_b2(const __half* __restrict__ A, const __half* __restrict__ B,
          const float* __restrict__ bias, __half* __restrict__ Cf)
{
    __shared__ __align__(16) __half sm2[2][5120];

    const int tid = threadIdx.x, warp = tid >> 5, lane = tid & 31;
    const int wm = warp & 1, wn = warp >> 1;
    const int gid = lane >> 2, tig = lane & 3;
    const int bm = blockIdx.x * 64, bn = 0;
    const int K = 256;

    float acc[2][4][4] = {};
    uint4 pa[2], pb[2];

    auto prefetch = [&](int it) {
        const int k0 = it * 32;
        #pragma unroll
        for (int s = 0; s < 2; s++) {
            int idx = tid + s * 128;
            int r = idx >> 2, kq = idx & 3;
            pa[s] = *(const uint4*)(A + (size_t)(bm + r) * K + k0 + kq * 8);
            pb[s] = *(const uint4*)(B + (size_t)r * K + k0 + kq * 8);
        }
    };

    prefetch(0);
    for (int it = 0; it < 8; it++) {
        __half* As = sm2[it & 1];
        __half* Bs = sm2[it & 1] + 2560;
        #pragma unroll
        for (int s = 0; s < 2; s++) {
            int idx = tid + s * 128;
            int r = idx >> 2, kq = idx & 3;
            *(uint4*)&As[r * LDA + kq * 8] = pa[s];
            *(uint4*)&Bs[r * LDA + kq * 8] = pb[s];
        }
        __syncthreads();
        if (it + 1 < 8) prefetch(it + 1);
        mma_chunk(As, Bs, wm, wn, gid, tig, acc);
    }
    gemm_epi(acc, bias, bm, bn, wm, wn, gid, tig, 1, Cf, FSTR);
}

// ======= b0: K=32 (13 real), fp32 inputs converted inline ======================
__global__ __launch_bounds__(256)
void k_b0(const float* __restrict__ dense, const float* __restrict__ W0,
          const float* __restrict__ bias, __half* __restrict__ h1)
{
    __shared__ __align__(16) __half sm0[7680];
    __half* As = sm0;
    __half* Bs = sm0 + 5120;
    const int tid = threadIdx.x, warp = tid >> 5, lane = tid & 31;
    const int wm = warp & 3, wn = warp >> 2;
    const int gid = lane >> 2, tig = lane & 3;
    const int bm = blockIdx.y * 128, bn = blockIdx.x * 64;

    #pragma unroll
    for (int s = 0; s < 8; s++) {
        int idx = tid + s * 256;
        int r = idx >> 4, cp = (idx & 15) * 2;
        float x0 = (cp < 13)     ? dense[(size_t)(bm + r) * 13 + cp]     : 0.f;
        float x1 = (cp + 1 < 13) ? dense[(size_t)(bm + r) * 13 + cp + 1] : 0.f;
        *(__half2*)&As[r * LDA + cp] = __floats2half2_rn(x0, x1);
    }
    #pragma unroll
    for (int s = 0; s < 8; s++) {
        int idx = tid + s * 256;
        int n = idx & 63, k = idx >> 6;
        float v = (k < 13) ? W0[(size_t)k * 512 + bn + n] : 0.f;
        Bs[n * LDA + k] = __float2half_rn(v);
    }
    __syncthreads();

    float acc[2][4][4] = {};
    mma_chunk(As, Bs, wm, wn, gid, tig, acc);
    gemm_epi(acc, bias, bm, bn, wm, wn, gid, tig, 1, h1, 512);
}

// ======= all weight splits in one launch ========================================
__device__ void split_role(int local, const float* __restrict__ W, int K, int N,
                           int Kpad, __half* __restrict__ o)
{
    int idx = local * 256 + threadIdx.x;
    if (idx >= N * Kpad) return;
    int n = idx / Kpad, k = idx - n * Kpad;
    float v = (k < K) ? W[(size_t)k * N + n] : 0.f;
    o[idx] = __float2half_rn(v);
}

__global__ __launch_bounds__(256)
void k_split(const float* W1, __half* w1, const float* W2, __half* w2,
             const float* T0, __half* t0, const float* T1, __half* t1)
{
    int blk = blockIdx.x;
    if (blk < 512)       split_role(blk,        W1, 512, 256, 512,  w1);
    else if (blk < 576)  split_role(blk - 512,  W2, 256, 64,  256,  w2);
    else if (blk < 1408) split_role(blk - 576,  T0, 415, 512, YSTR, t0);
    else                 split_role(blk - 1408, T1, 512, 256, 512,  t1);
}

// ======= embedding gather + pool: 2 tasks per warp (MLP 8), fp16 output ========
__global__ __launch_bounds__(256)
void k_gather(const void* __restrict__ idx_raw,
              const float* __restrict__ tables, __half* __restrict__ feats)
{
    const int gwarp = (blockIdx.x * blockDim.x + threadIdx.x) >> 5;
    const int lane = threadIdx.x & 31;
    const long long t0 = (long long)gwarp * 2;

    const long long* p64 = (const long long*)idx_raw;
    long long v0 = p64[0], v1 = p64[123], v2 = p64[4567], v3 = p64[89012];
    const bool is64 = (v0 >= 0 && v0 < Nrows) && (v1 >= 0 && v1 < Nrows) &&
                      (v2 >= 0 && v2 < Nrows) && (v3 >= 0 && v3 < Nrows);
    const int* p32 = (const int*)idx_raw;

    int f[2], b[2];
    long long rows[2][Lk];
    #pragma unroll
    for (int u = 0; u < 2; u++) {
        long long t = t0 + u;
        f[u] = (int)(t / Bsz); b[u] = (int)(t % Bsz);
        long long base = (long long)f[u] * Bsz * Lk + (long long)b[u] * Lk;
        #pragma unroll
        for (int l = 0; l < Lk; l++)
            rows[u][l] = is64 ? p64[base + l] : (long long)p32[base + l];
    }

    float2 v[2][Lk];
    #pragma unroll
    for (int u = 0; u < 2; u++)
        #pragma unroll
        for (int l = 0; l < Lk; l++)
            v[u][l] = *(const float2*)(tables +
                ((long long)f[u] * Nrows + rows[u][l]) * Dim + lane * 2);

    #pragma unroll
    for (int u = 0; u < 2; u++) {
        float2 acc = make_float2(0.f, 0.f);
        #pragma unroll
        for (int l = 0; l < Lk; l++) { acc.x += v[u][l].x; acc.y += v[u][l].y; }
        *(__half2*)(feats + (size_t)b[u] * FSTR + (f[u] + 1) * Dim + lane * 2) =
            __floats2half2_rn(acc.x, acc.y);
    }
}

// ======= interaction: 1 warp/sample, 1-term fp16 gram ==========================
__global__ __launch_bounds__(128)
void interact_mma(const __half* __restrict__ feats, __half* __restrict__ y)
{
    __shared__ __half sF[4][32 * ILD];
    const int warp = threadIdx.x >> 5, lane = threadIdx.x & 31;
    const int b = blockIdx.x * 4 + warp;
    const int gid = lane >> 2, tig = lane & 3;
    __half* Fh = &sF[warp][0];
    const __half* fr = feats + (size_t)b * FSTR;

    #pragma unroll
    for (int s = 0; s < 8; s++) {
        int idx = lane + s * 32;
        int r = idx >> 3, q = idx & 7;
        uint4 vv = make_uint4(0u, 0u, 0u, 0u);
        if (r < NFEAT) vv = *(const uint4*)(fr + r * 64 + q * 8);
        *(uint4*)&Fh[r * ILD + q * 8] = vv;
    }
    __syncwarp();

    float acc[2][4][4] = {};
    #pragma unroll
    for (int ks = 0; ks < 64; ks += 16) {
        uint32_t ah[2][4], bh[4][2];
        #pragma unroll
        for (int mt = 0; mt < 2; mt++) {
            int r0 = (mt * 16 + gid) * ILD + ks + 2 * tig;
            ah[mt][0] = *(const uint32_t*)&Fh[r0];
            ah[mt][1] = *(const uint32_t*)&Fh[r0 + 8 * ILD];
            ah[mt][2] = *(const uint32_t*)&Fh[r0 + 8];
            ah[mt][3] = *(const uint32_t*)&Fh[r0 + 8 * ILD + 8];
        }
        #pragma unroll
        for (int nt = 0; nt < 4; nt++) {
            int n0 = (nt * 8 + gid) * ILD + ks + 2 * tig;
            bh[nt][0] = *(const uint32_t*)&Fh[n0];
            bh[nt][1] = *(const uint32_t*)&Fh[n0 + 8];
        }
        #pragma unroll
        for (int mt = 0; mt < 2; mt++)
            #pragma unroll
            for (int nt = 0; nt < 4; nt++)
                MMA_F16(acc[mt][nt], ah[mt], bh[nt][0], bh[nt][1]);
    }

    __half* yr = y + (size_t)b * YSTR;
    #pragma unroll
    for (int s = 0; s < 2; s++) yr[lane + s * 32] = Fh[lane + s * 32];
    if (lane == 0) yr[OVERIN] = __float2half_rn(0.f);

    #pragma unroll
    for (int mt = 0; mt < 2; mt++)
        #pragma unroll
        for (int nt = 0; nt < 4; nt++)
            #pragma unroll
            for (int e = 0; e < 4; e++) {
                int m = mt * 16 + gid + (e >> 1) * 8;
                int n = nt * 8 + tig * 2 + (e & 1);
                if (n > m && n < NFEAT) {
                    int p = m * (2 * NFEAT - m - 1) / 2 + (n - m - 1);
                    yr[Dim + p] = __float2half_rn(acc[mt][nt][e]);
                }
            }
}

// ======= final layer ============================================================
__global__ __launch_bounds__(256)
void gemv_final(const __half* __restrict__ X, const float* __restrict__ w,
                const float* __restrict__ bias, float* __restrict__ out)
{
    const int row = (blockIdx.x * blockDim.x + threadIdx.x) >> 5;
    const int lane = threadIdx.x & 31;
    if (row >= Bsz) return;
    uint4 hv = *(const uint4*)(X + (size_t)row * 256 + lane * 8);
    const __half2* hp = (const __half2*)&hv;
    float s = 0.f;
    #pragma unroll
    for (int q = 0; q < 4; q++) {
        float2 h2 = __half22float2(hp[q]);
        s = fmaf(h2.x, w[lane * 8 + q * 2], s);
        s = fmaf(h2.y, w[lane * 8 + q * 2 + 1], s);
    }
    #pragma unroll
    for (int o = 16; o; o >>= 1) s += __shfl_down_sync(0xffffffffu, s, o);
    if (lane == 0) out[row] = s + bias[0];
}

// -----------------------------------------------------------------------------
static void* sym_addr(const void* sym)
{
    void* p = nullptr;
    cudaGetSymbolAddress(&p, sym);
    return p;
}

extern "C" void kernel_launch(void* const* d_in, const int* in_sizes, int n_in,
                              void* d_out, int out_size)
{
    (void)in_sizes; (void)n_in; (void)out_size;

    const float* dense  = (const float*)d_in[0];
    const void*  sp_idx = d_in[1];
    const float* tables = (const float*)d_in[2];
    const float* botW0 = (const float*)d_in[3],  *botb0 = (const float*)d_in[4];
    const float* botW1 = (const float*)d_in[5],  *botb1 = (const float*)d_in[6];
    const float* botW2 = (const float*)d_in[7],  *botb2 = (const float*)d_in[8];
    const float* topW0 = (const float*)d_in[9],  *topb0 = (const float*)d_in[10];
    const float* topW1 = (const float*)d_in[11], *topb1 = (const float*)d_in[12];
    const float* topW2 = (const float*)d_in[13], *topb2 = (const float*)d_in[14];
    float* out = (float*)d_out;

    __half* feats = (__half*)sym_addr(g_feats);
    __half* h1 = (__half*)sym_addr(g_h1);
    __half* h2 = (__half*)sym_addr(g_h2);
    __half* y  = (__half*)sym_addr(g_y);
    __half* w1 = (__half*)sym_addr(g_w1);
    __half* w2 = (__half*)sym_addr(g_w2);
    __half* t0 = (__half*)sym_addr(g_t0);
    __half* t1 = (__half*)sym_addr(g_t1);

    static int smem_set = 0;
    if (!smem_set) {
        cudaFuncSetAttribute(k_gemm,
            cudaFuncAttributeMaxDynamicSharedMemorySize, GSMEM);
        smem_set = 1;
    }

    // #1 splits, #2 b0, #3 gather, #4 b1 (profiled), #5 b2, #6 interact,
    // #7 t0, #8 t1, #9 gemv
    k_split<<<1920, 256>>>(botW1, w1, botW2, w2, topW0, t0, topW1, t1);
    k_b0<<<dim3(8, 128), 256>>>(dense, botW0, botb0, h1);
    k_gather<<<(Fn * Bsz / 2 * 32) / 256, 256>>>(sp_idx, tables, feats);
    k_gemm<<<dim3(2, 128), 256, GSMEM>>>(h1, w1, botb1, 512, h2, 256);
    k_b2<<<256, 128>>>(h2, w2, botb2, feats);
    interact_mma<<<Bsz / 4, 128>>>(feats, y);
    k_gemm<<<dim3(4, 128), 256, GSMEM>>>(y, t0, topb0, YSTR, h1, 512);
    k_gemm<<<dim3(2, 128), 256, GSMEM>>>(h1, t1, topb1, 512, h2, 256);
    gemv_final<<<(Bsz * 32) / 256, 256>>>(h2, topW2, topb2, out);
}